// round 3
// baseline (speedup 1.0000x reference)
#include <cuda_runtime.h>
#include <math.h>

#define BATCH 16384
#define NCO   64
#define NFI   128
#define NSF   192
#define HID   64

typedef unsigned long long ull;

// ---------------- scratch (device globals; no allocation allowed) ----------------
__device__ float g_rgb_c[BATCH * NCO * 3];
__device__ float g_sig_c[BATCH * NCO];
__device__ float g_z    [BATCH * NSF];
__device__ float g_rgb_f[BATCH * NSF * 3];
__device__ float g_sig_f[BATCH * NSF];

// ---------------- f32x2 helpers ----------------
__device__ __forceinline__ ull pk2(float lo, float hi) {
    ull r; asm("mov.b64 %0,{%1,%2};" : "=l"(r) : "f"(lo), "f"(hi)); return r;
}
__device__ __forceinline__ void up2(ull v, float& lo, float& hi) {
    asm("mov.b64 {%0,%1},%2;" : "=f"(lo), "=f"(hi) : "l"(v));
}
__device__ __forceinline__ ull ffma2_(ull a, ull b, ull c) {
    ull d; asm("fma.rn.f32x2 %0,%1,%2,%3;" : "=l"(d) : "l"(a), "l"(b), "l"(c)); return d;
}
__device__ __forceinline__ ull fadd2_(ull a, ull b) {
    ull d; asm("add.rn.f32x2 %0,%1,%2;" : "=l"(d) : "l"(a), "l"(b)); return d;
}
__device__ __forceinline__ ull relu2_(ull a) {
    float x, y; up2(a, x, y); return pk2(fmaxf(x, 0.f), fmaxf(y, 0.f));
}
__device__ __forceinline__ float sigmoidf_(float z) { return 1.0f / (1.0f + __expf(-z)); }

// ---------------- packed MLP: one thread per sample PAIR ----------------
// Block = 128 threads = 256 samples per tile, 8 tiles per block.
template <int NS, bool COARSE>
__global__ void __launch_bounds__(128) mlp2_kernel(
    const float* __restrict__ org,  const float* __restrict__ dirv,
    const float* __restrict__ nearp,const float* __restrict__ farp,
    const float* __restrict__ w1,   const float* __restrict__ b1,
    const float* __restrict__ w2,   const float* __restrict__ b2,
    const float* __restrict__ wr,   const float* __restrict__ br,
    const float* __restrict__ wd,   const float* __restrict__ bd)
{
    __shared__ __align__(16) ull sW1d[3 * HID];     // dup (w,w), [k][j]
    __shared__ __align__(16) ull sB1d[HID];
    __shared__ __align__(16) ull sW2d[HID * HID];   // dup, TRANSPOSED: [j][k]
    __shared__ __align__(16) ull sB2d[HID];
    __shared__ __align__(16) ull sHd[HID * 4];      // [j][{wr0,wr1,wr2,wd}] dup
    __shared__ float sBh[4];

    const int tid = threadIdx.x;
    for (int i = tid; i < HID * HID; i += 128) {
        int j = i >> 6, k = i & 63;
        float w = w2[k * HID + j];
        sW2d[i] = pk2(w, w);
    }
    for (int i = tid; i < 3 * HID; i += 128) { float w = w1[i]; sW1d[i] = pk2(w, w); }
    if (tid < HID) { sB1d[tid] = pk2(b1[tid], b1[tid]); sB2d[tid] = pk2(b2[tid], b2[tid]); }
    for (int i = tid; i < HID * 4; i += 128) {
        int j = i >> 2, c = i & 3;
        float w = (c < 3) ? wr[j * 3 + c] : wd[j];
        sHd[i] = pk2(w, w);
    }
    if (tid == 0) { sBh[0] = br[0]; sBh[1] = br[1]; sBh[2] = br[2]; sBh[3] = bd[0]; }
    __syncthreads();

    const int TILES = 8;
    for (int tile = 0; tile < TILES; tile++) {
        const int p  = (blockIdx.x * TILES + tile) * 128 + tid;  // pair index
        const int s0 = 2 * p;
        const int b  = s0 / NS;
        const int ii = s0 - b * NS;

        float t0, t1;
        if (COARSE) {
            const float nb = nearp[b], fb = farp[b];
            float q0 = (float)ii * (1.0f / (float)(NS - 1));
            float q1 = (ii + 1 == NS - 1) ? 1.0f : (float)(ii + 1) * (1.0f / (float)(NS - 1));
            t0 = nb * (1.0f - q0) + fb * q0;
            t1 = nb * (1.0f - q1) + fb * q1;
        } else {
            float2 zz = ((const float2*)g_z)[p];
            t0 = zz.x; t1 = zz.y;
        }
        const float ox = org[3 * b], oy = org[3 * b + 1], oz = org[3 * b + 2];
        const float dx = dirv[3 * b], dy = dirv[3 * b + 1], dz = dirv[3 * b + 2];
        const ull xp0 = pk2(fmaf(t0, dx, ox), fmaf(t1, dx, ox));
        const ull xp1 = pk2(fmaf(t0, dy, oy), fmaf(t1, dy, oy));
        const ull xp2 = pk2(fmaf(t0, dz, oz), fmaf(t1, dz, oz));

        // layer 1
        ull h1[HID];
#pragma unroll
        for (int j = 0; j < HID; j++) {
            ull a = ffma2_(xp0, sW1d[j], sB1d[j]);
            a = ffma2_(xp1, sW1d[HID + j], a);
            a = ffma2_(xp2, sW1d[2 * HID + j], a);
            h1[j] = relu2_(a);
        }

        // layer 2 streamed into heads
        ull r0 = pk2(sBh[0], sBh[0]);
        ull r1 = pk2(sBh[1], sBh[1]);
        ull r2 = pk2(sBh[2], sBh[2]);
        ull dn = pk2(sBh[3], sBh[3]);

#pragma unroll 1
        for (int j = 0; j < HID; j += 2) {
            const ulonglong2* rowA = (const ulonglong2*)&sW2d[j << 6];
            const ulonglong2* rowB = (const ulonglong2*)&sW2d[(j + 1) << 6];
            ull aA0 = sB2d[j],     aA1 = 0ull;
            ull aB0 = sB2d[j + 1], aB1 = 0ull;
#pragma unroll
            for (int kk = 0; kk < 32; kk++) {
                ulonglong2 wa = rowA[kk];
                ulonglong2 wb = rowB[kk];
                aA0 = ffma2_(h1[2 * kk],     wa.x, aA0);
                aA1 = ffma2_(h1[2 * kk + 1], wa.y, aA1);
                aB0 = ffma2_(h1[2 * kk],     wb.x, aB0);
                aB1 = ffma2_(h1[2 * kk + 1], wb.y, aB1);
            }
            const ull h2a = relu2_(fadd2_(aA0, aA1));
            const ull h2b = relu2_(fadd2_(aB0, aB1));
            const ulonglong2* hd = (const ulonglong2*)&sHd[j << 2];
            ulonglong2 hA0 = hd[0], hA1 = hd[1], hB0 = hd[2], hB1 = hd[3];
            r0 = ffma2_(h2a, hA0.x, r0); r1 = ffma2_(h2a, hA0.y, r1);
            r2 = ffma2_(h2a, hA1.x, r2); dn = ffma2_(h2a, hA1.y, dn);
            r0 = ffma2_(h2b, hB0.x, r0); r1 = ffma2_(h2b, hB0.y, r1);
            r2 = ffma2_(h2b, hB1.x, r2); dn = ffma2_(h2b, hB1.y, dn);
        }

        float ra, rb, ga, gb, ba, bb, da, db;
        up2(r0, ra, rb); up2(r1, ga, gb); up2(r2, ba, bb); up2(dn, da, db);
        float* rc = (COARSE ? g_rgb_c : g_rgb_f) + (size_t)3 * s0;
        rc[0] = sigmoidf_(ra); rc[1] = sigmoidf_(ga); rc[2] = sigmoidf_(ba);
        rc[3] = sigmoidf_(rb); rc[4] = sigmoidf_(gb); rc[5] = sigmoidf_(bb);
        ((float2*)(COARSE ? g_sig_c : g_sig_f))[p] =
            make_float2(fmaxf(da, 0.f), fmaxf(db, 0.f));
    }
}

// ---------------- coarse render + inverse-CDF sampling + sorted merge (R1 scalar, verbatim) ----------------
__global__ void coarse_post_kernel(
    const float* __restrict__ org, const float* __restrict__ dirv,
    const float* __restrict__ nearp, const float* __restrict__ farp,
    const float* __restrict__ bkgd, float* __restrict__ out)
{
    const int b = blockIdx.x * blockDim.x + threadIdx.x;
    if (b >= BATCH) return;

    const float nb = nearp[b], fb = farp[b];
    const float n0 = nearp[0], f0 = farp[0];
    const float dxx = dirv[3*b+0], dyy = dirv[3*b+1], dzz = dirv[3*b+2];
    const float nrm = sqrtf(dxx*dxx + dyy*dyy + dzz*dzz);
    const float o0x = org[0],  o0y = org[1],  o0z = org[2];
    const float d0x = dirv[0], d0y = dirv[1], d0z = dirv[2];

    auto TV  = [&](int i) -> float {
        float tq = (i == 63) ? 1.0f : (float)i * (1.0f / 63.0f);
        return nb * (1.0f - tq) + fb * tq;
    };
    auto TV0 = [&](int i) -> float {
        float tq = (i == 63) ? 1.0f : (float)i * (1.0f / 63.0f);
        return n0 * (1.0f - tq) + f0 * tq;
    };

    // volumetric rendering (exclusive-cumsum transmittance)
    float w[NCO];
    float S = 0.f, acc = 0.f, depth = 0.f, wt0 = 0.f, c0 = 0.f, c1 = 0.f, c2 = 0.f;
    float tcur = TV(0);
    for (int i = 0; i < NCO; i++) {
        const float tnext = (i < 63) ? TV(i + 1) : tcur;
        const float td    = (i < 63) ? (tnext - tcur) : 1e10f;
        const float dd    = g_sig_c[b * NCO + i] * td * nrm;
        const float T     = __expf(-S);
        const float alpha = 1.0f - __expf(-dd);
        const float wi    = alpha * T;
        S += dd;
        w[i] = wi;
        acc += wi;
        depth = fmaf(wi, tcur, depth);
        wt0   = fmaf(wi, TV0(i), wt0);
        const float* rp = &g_rgb_c[(size_t)(b * NCO + i) * 3];
        c0 = fmaf(wi, rp[0], c0);
        c1 = fmaf(wi, rp[1], c1);
        c2 = fmaf(wi, rp[2], c2);
        tcur = tnext;
    }
    float* ob = out + (size_t)b * 16;
    ob[0] = c0 + bkgd[0] * (1.0f - acc);
    ob[1] = c1 + bkgd[1] * (1.0f - acc);
    ob[2] = c2 + bkgd[2] * (1.0f - acc);
    ob[3] = depth;
    ob[4] = acc;
    ob[5] = acc * o0x + wt0 * d0x;   // pts0 uses samples[0] (ray-0 positions)
    ob[6] = acc * o0y + wt0 * d0y;
    ob[7] = acc * o0z + wt0 * d0z;

    // piecewise-constant pdf over w[1..62]
    float ws = 0.f;
    for (int k = 1; k <= 62; k++) ws += w[k];
    const float pad = fmaxf(1e-5f - ws, 0.0f);
    const float add = pad * (1.0f / 62.0f);
    ws += pad;
    const float inv = 1.0f / ws;
    float cdf[64];
    cdf[0] = 0.0f;
    float cs = 0.f;
    for (int k = 1; k <= 61; k++) {
        cs += (w[k] + add) * inv;
        cdf[k] = fminf(cs, 1.0f);
    }
    cdf[62] = 1.0f;

    auto BIN = [&](int k) -> float { return 0.5f * (TV(k) + TV(k + 1)); };

    // inverse-CDF samples for sorted u, merged inline with sorted t_vals
    const float ueps = 1.1920929e-07f;
    const float du = (1.0f - ueps) * (1.0f / 127.0f);
    int idx = 0, ti = 0, p = 0;
    const size_t base = (size_t)b * NSF;
    for (int s = 0; s < NFI; s++) {
        const float u = (s == 127) ? (1.0f - ueps) : (float)s * du;
        while (idx < 61 && cdf[idx + 1] <= u) idx++;
        const float gg0 = cdf[idx], gg1 = cdf[idx + 1];
        float tt = (u - gg0) / (gg1 - gg0);
        if (!(tt == tt)) tt = 0.0f;          // nan -> 0; +inf clips to 1 below
        tt = fminf(fmaxf(tt, 0.0f), 1.0f);
        const float bb0 = BIN(idx);
        const float z = fmaf(tt, BIN(idx + 1) - bb0, bb0);
        while (ti < NCO && TV(ti) <= z) { g_z[base + p] = TV(ti); p++; ti++; }
        g_z[base + p] = z; p++;
    }
    while (ti < NCO) { g_z[base + p] = TV(ti); p++; ti++; }
}

// ---------------- fine render (R1 scalar, verbatim) ----------------
__global__ void fine_render_kernel(
    const float* __restrict__ org, const float* __restrict__ dirv,
    const float* __restrict__ bkgd, float* __restrict__ out)
{
    const int b = blockIdx.x * blockDim.x + threadIdx.x;
    if (b >= BATCH) return;

    const float dxx = dirv[3*b+0], dyy = dirv[3*b+1], dzz = dirv[3*b+2];
    const float nrm = sqrtf(dxx*dxx + dyy*dyy + dzz*dzz);
    const float o0x = org[0],  o0y = org[1],  o0z = org[2];
    const float d0x = dirv[0], d0y = dirv[1], d0z = dirv[2];

    const float* zr = g_z + (size_t)b * NSF;
    float S = 0.f, acc = 0.f, depth = 0.f, wz0 = 0.f, c0 = 0.f, c1 = 0.f, c2 = 0.f;
    float zc = zr[0];
    for (int i = 0; i < NSF; i++) {
        const float znext = (i < NSF - 1) ? zr[i + 1] : zc;
        const float td    = (i < NSF - 1) ? (znext - zc) : 1e10f;
        const float dd    = g_sig_f[(size_t)b * NSF + i] * td * nrm;
        const float T     = __expf(-S);
        const float alpha = 1.0f - __expf(-dd);
        const float wi    = alpha * T;
        S += dd;
        acc += wi;
        depth = fmaf(wi, zc, depth);
        wz0   = fmaf(wi, g_z[i], wz0);   // samples_f[0] quirk: ray-0 z positions
        const float* rp = &g_rgb_f[((size_t)b * NSF + i) * 3];
        c0 = fmaf(wi, rp[0], c0);
        c1 = fmaf(wi, rp[1], c1);
        c2 = fmaf(wi, rp[2], c2);
        zc = znext;
    }
    float* ob = out + (size_t)b * 16;
    ob[8]  = c0 + bkgd[0] * (1.0f - acc);
    ob[9]  = c1 + bkgd[1] * (1.0f - acc);
    ob[10] = c2 + bkgd[2] * (1.0f - acc);
    ob[11] = depth;
    ob[12] = acc;
    ob[13] = acc * o0x + wz0 * d0x;
    ob[14] = acc * o0y + wz0 * d0y;
    ob[15] = acc * o0z + wz0 * d0z;
}

// ---------------- launch ----------------
extern "C" void kernel_launch(void* const* d_in, const int* in_sizes, int n_in,
                              void* d_out, int out_size)
{
    const float* org   = (const float*)d_in[0];
    const float* dirv  = (const float*)d_in[1];
    const float* nearp = (const float*)d_in[2];
    const float* farp  = (const float*)d_in[3];
    const float* bkgd  = (const float*)d_in[4];

    const float* w1c = (const float*)d_in[5];
    const float* b1c = (const float*)d_in[6];
    const float* w2c = (const float*)d_in[7];
    const float* b2c = (const float*)d_in[8];
    const float* wrc = (const float*)d_in[9];
    const float* brc = (const float*)d_in[10];
    const float* wdc = (const float*)d_in[11];
    const float* bdc = (const float*)d_in[12];

    const float* w1f = (const float*)d_in[13];
    const float* b1f = (const float*)d_in[14];
    const float* w2f = (const float*)d_in[15];
    const float* b2f = (const float*)d_in[16];
    const float* wrf = (const float*)d_in[17];
    const float* brf = (const float*)d_in[18];
    const float* wdf = (const float*)d_in[19];
    const float* bdf = (const float*)d_in[20];

    float* out = (float*)d_out;

    // coarse MLP: 16384*64 samples / (256 samples * 8 tiles) = 512 blocks
    mlp2_kernel<NCO, true><<<512, 128>>>(
        org, dirv, nearp, farp, w1c, b1c, w2c, b2c, wrc, brc, wdc, bdc);

    // scalar per-ray, 32-thread blocks to spread over all SMs
    coarse_post_kernel<<<BATCH / 32, 32>>>(org, dirv, nearp, farp, bkgd, out);

    // fine MLP: 16384*192 / 2048 = 1536 blocks
    mlp2_kernel<NSF, false><<<1536, 128>>>(
        org, dirv, nearp, farp, w1f, b1f, w2f, b2f, wrf, brf, wdf, bdf);

    fine_render_kernel<<<BATCH / 32, 32>>>(org, dirv, bkgd, out);
}

// round 5
// speedup vs baseline: 2.4414x; 2.4414x over previous
#include <cuda_runtime.h>
#include <math.h>

#define BATCH 16384
#define NCO   64
#define NFI   128
#define NSF   192
#define HID   64

// ---------------- scratch (device globals; no allocation allowed) ----------------
__device__ float g_rgb_c[BATCH * NCO * 3];
__device__ float g_sig_c[BATCH * NCO];
__device__ float g_z    [BATCH * NSF];
__device__ float g_rgb_f[BATCH * NSF * 3];
__device__ float g_sig_f[BATCH * NSF];

__device__ __forceinline__ float sigmoidf_(float z) { return 1.0f / (1.0f + __expf(-z)); }

__device__ __forceinline__ unsigned tf32_rna(float v) {
    unsigned r; asm("cvt.rna.tf32.f32 %0, %1;" : "=r"(r) : "f"(v)); return r;
}
__device__ __forceinline__ void mma_tf32(float& c0, float& c1, float& c2, float& c3,
    unsigned a0, unsigned a1, unsigned a2, unsigned a3, unsigned b0, unsigned b1) {
    asm("mma.sync.aligned.m16n8k8.row.col.f32.tf32.tf32.f32 "
        "{%0,%1,%2,%3},{%4,%5,%6,%7},{%8,%9},{%0,%1,%2,%3};"
        : "+f"(c0), "+f"(c1), "+f"(c2), "+f"(c3)
        : "r"(a0), "r"(a1), "r"(a2), "r"(a3), "r"(b0), "r"(b1));
}

// W2 smem layout: [k][n], row stride 72 floats (72 mod 32 == 8 -> bank(8*tig+gid) bijective,
// conflict-free B-fragment loads).
#define W2S 72

// ---------------- MLP via mma.sync tf32 (3xTF32), warp per 16-sample tile ----------------
// Block = 128 threads = 4 warps; each warp does TPW tiles of 16 samples.
template <int NS, bool COARSE, int TPW>
__global__ void __launch_bounds__(128) mlp_mma_kernel(
    const float* __restrict__ org,  const float* __restrict__ dirv,
    const float* __restrict__ nearp,const float* __restrict__ farp,
    const float* __restrict__ w1,   const float* __restrict__ b1,
    const float* __restrict__ w2,   const float* __restrict__ b2,
    const float* __restrict__ wr,   const float* __restrict__ br,
    const float* __restrict__ wd,   const float* __restrict__ bd)
{
    __shared__ float sW2hi[HID * W2S];
    __shared__ float sW2lo[HID * W2S];
    __shared__ __align__(16) float sL1[HID * 4];   // (w1_0, w1_1, w1_2, b1) per hidden unit
    __shared__ __align__(16) float sHD[HID * 4];   // (wr0, wr1, wr2, wd) per hidden unit
    __shared__ float sB2[HID];
    __shared__ float sBh[4];

    const int tid = threadIdx.x;
    for (int i = tid; i < HID * HID; i += 128) {
        int k = i >> 6, n = i & 63;
        float v = w2[i];                       // w2 row-major [k][n]
        unsigned hu = tf32_rna(v);
        float hf = __uint_as_float(hu);
        sW2hi[k * W2S + n] = hf;
        sW2lo[k * W2S + n] = __uint_as_float(tf32_rna(v - hf));
    }
    for (int i = tid; i < HID; i += 128) {
        sL1[4*i+0] = w1[i]; sL1[4*i+1] = w1[64+i]; sL1[4*i+2] = w1[128+i]; sL1[4*i+3] = b1[i];
        sHD[4*i+0] = wr[3*i]; sHD[4*i+1] = wr[3*i+1]; sHD[4*i+2] = wr[3*i+2]; sHD[4*i+3] = wd[i];
        sB2[i] = b2[i];
    }
    if (tid == 0) { sBh[0] = br[0]; sBh[1] = br[1]; sBh[2] = br[2]; sBh[3] = bd[0]; }
    __syncthreads();

    const int lane = tid & 31;
    const int gid  = lane >> 2;   // 0..7 : sample rows gid, gid+8
    const int tig  = lane & 3;    // 0..3 : k/n sub-index
    const int warpGlobal = blockIdx.x * 4 + (tid >> 5);

#pragma unroll 1
    for (int it = 0; it < TPW; ++it) {
        const int tileIdx = warpGlobal * TPW + it;
        const int s0 = tileIdx * 16;
        const int b  = s0 / NS;                 // 16 | NS -> tile within one ray

        const float ox = org[3*b], oy = org[3*b+1], oz = org[3*b+2];
        const float dx = dirv[3*b], dy = dirv[3*b+1], dz = dirv[3*b+2];
        float t0, t1;
        if (COARSE) {
            const float nb = nearp[b], fb = farp[b];
            const int i0 = (s0 % NS) + gid, i1 = i0 + 8;
            float q0 = (i0 == 63) ? 1.0f : (float)i0 * (1.0f / 63.0f);
            float q1 = (i1 == 63) ? 1.0f : (float)i1 * (1.0f / 63.0f);
            t0 = nb * (1.0f - q0) + fb * q0;
            t1 = nb * (1.0f - q1) + fb * q1;
        } else {
            t0 = g_z[s0 + gid];
            t1 = g_z[s0 + gid + 8];
        }
        const float x00 = fmaf(t0, dx, ox), x01 = fmaf(t0, dy, oy), x02 = fmaf(t0, dz, oz);
        const float x10 = fmaf(t1, dx, ox), x11 = fmaf(t1, dy, oy), x12 = fmaf(t1, dz, oz);

        // ---- layer 1 (scalar fp32) straight into A fragments (hi/lo tf32 split) ----
        // lane owns h1 cols c = 4m + tig, m=0..15, rows gid (A0) / gid+8 (A1).
        unsigned Ahi0[16], Alo0[16], Ahi1[16], Alo1[16];
#pragma unroll
        for (int m = 0; m < 16; m++) {
            const int c = 4 * m + tig;
            const float4 L = *(const float4*)&sL1[4 * c];
            const float hA = fmaxf(fmaf(x02, L.z, fmaf(x01, L.y, fmaf(x00, L.x, L.w))), 0.0f);
            const float hB = fmaxf(fmaf(x12, L.z, fmaf(x11, L.y, fmaf(x10, L.x, L.w))), 0.0f);
            const unsigned ha = tf32_rna(hA);
            Ahi0[m] = ha; Alo0[m] = tf32_rna(hA - __uint_as_float(ha));
            const unsigned hb = tf32_rna(hB);
            Ahi1[m] = hb; Alo1[m] = tf32_rna(hB - __uint_as_float(hb));
        }

        // ---- layer 2 via mma (3xTF32) + streamed heads ----
        float hp0[4] = {0.f, 0.f, 0.f, 0.f};   // head partials, sample row gid
        float hp1[4] = {0.f, 0.f, 0.f, 0.f};   // head partials, sample row gid+8
#pragma unroll 1
        for (int nc = 0; nc < 8; nc++) {
            const int j0 = nc * 8 + 2 * tig;   // output cols this lane accumulates
            const int nB = nc * 8 + gid;       // B-fragment n index
            float c0 = sB2[j0], c1 = sB2[j0 + 1];
            float c2 = c0, c3 = c1;
#pragma unroll
            for (int kc = 0; kc < 8; kc++) {
                const int kr = kc * 8 + tig;
                const unsigned bh0 = __float_as_uint(sW2hi[kr * W2S + nB]);
                const unsigned bh1 = __float_as_uint(sW2hi[(kr + 4) * W2S + nB]);
                const unsigned bl0 = __float_as_uint(sW2lo[kr * W2S + nB]);
                const unsigned bl1 = __float_as_uint(sW2lo[(kr + 4) * W2S + nB]);
                mma_tf32(c0, c1, c2, c3,
                         Ahi0[2*kc], Ahi1[2*kc], Ahi0[2*kc+1], Ahi1[2*kc+1], bh0, bh1);
                mma_tf32(c0, c1, c2, c3,
                         Alo0[2*kc], Alo1[2*kc], Alo0[2*kc+1], Alo1[2*kc+1], bh0, bh1);
                mma_tf32(c0, c1, c2, c3,
                         Ahi0[2*kc], Ahi1[2*kc], Ahi0[2*kc+1], Ahi1[2*kc+1], bl0, bl1);
            }
            // heads for this lane's two output cols (relu(h2) dot head weights)
            const float4 H0 = *(const float4*)&sHD[4 * j0];
            const float4 H1 = *(const float4*)&sHD[4 * (j0 + 1)];
            const float v00 = fmaxf(c0, 0.f), v01 = fmaxf(c1, 0.f);
            const float v10 = fmaxf(c2, 0.f), v11 = fmaxf(c3, 0.f);
            hp0[0] = fmaf(v00, H0.x, fmaf(v01, H1.x, hp0[0]));
            hp0[1] = fmaf(v00, H0.y, fmaf(v01, H1.y, hp0[1]));
            hp0[2] = fmaf(v00, H0.z, fmaf(v01, H1.z, hp0[2]));
            hp0[3] = fmaf(v00, H0.w, fmaf(v01, H1.w, hp0[3]));
            hp1[0] = fmaf(v10, H0.x, fmaf(v11, H1.x, hp1[0]));
            hp1[1] = fmaf(v10, H0.y, fmaf(v11, H1.y, hp1[1]));
            hp1[2] = fmaf(v10, H0.z, fmaf(v11, H1.z, hp1[2]));
            hp1[3] = fmaf(v10, H0.w, fmaf(v11, H1.w, hp1[3]));
        }

        // reduce head partials across the 4 tig lanes of each row group
#pragma unroll
        for (int c = 0; c < 4; c++) {
            hp0[c] += __shfl_xor_sync(0xffffffffu, hp0[c], 1);
            hp0[c] += __shfl_xor_sync(0xffffffffu, hp0[c], 2);
            hp1[c] += __shfl_xor_sync(0xffffffffu, hp1[c], 1);
            hp1[c] += __shfl_xor_sync(0xffffffffu, hp1[c], 2);
        }
        if (tig == 0) {
            float* rgb = COARSE ? g_rgb_c : g_rgb_f;
            float* sg  = COARSE ? g_sig_c : g_sig_f;
            const int sA = s0 + gid, sB = s0 + gid + 8;
            rgb[3*sA+0] = sigmoidf_(hp0[0] + sBh[0]);
            rgb[3*sA+1] = sigmoidf_(hp0[1] + sBh[1]);
            rgb[3*sA+2] = sigmoidf_(hp0[2] + sBh[2]);
            sg[sA] = fmaxf(hp0[3] + sBh[3], 0.f);
            rgb[3*sB+0] = sigmoidf_(hp1[0] + sBh[0]);
            rgb[3*sB+1] = sigmoidf_(hp1[1] + sBh[1]);
            rgb[3*sB+2] = sigmoidf_(hp1[2] + sBh[2]);
            sg[sB] = fmaxf(hp1[3] + sBh[3], 0.f);
        }
    }
}

// ---------------- coarse render + inverse-CDF sampling + sorted merge (R3 scalar, verbatim) ----------------
__global__ void coarse_post_kernel(
    const float* __restrict__ org, const float* __restrict__ dirv,
    const float* __restrict__ nearp, const float* __restrict__ farp,
    const float* __restrict__ bkgd, float* __restrict__ out)
{
    const int b = blockIdx.x * blockDim.x + threadIdx.x;
    if (b >= BATCH) return;

    const float nb = nearp[b], fb = farp[b];
    const float n0 = nearp[0], f0 = farp[0];
    const float dxx = dirv[3*b+0], dyy = dirv[3*b+1], dzz = dirv[3*b+2];
    const float nrm = sqrtf(dxx*dxx + dyy*dyy + dzz*dzz);
    const float o0x = org[0],  o0y = org[1],  o0z = org[2];
    const float d0x = dirv[0], d0y = dirv[1], d0z = dirv[2];

    auto TV  = [&](int i) -> float {
        float tq = (i == 63) ? 1.0f : (float)i * (1.0f / 63.0f);
        return nb * (1.0f - tq) + fb * tq;
    };
    auto TV0 = [&](int i) -> float {
        float tq = (i == 63) ? 1.0f : (float)i * (1.0f / 63.0f);
        return n0 * (1.0f - tq) + f0 * tq;
    };

    float w[NCO];
    float S = 0.f, acc = 0.f, depth = 0.f, wt0 = 0.f, c0 = 0.f, c1 = 0.f, c2 = 0.f;
    float tcur = TV(0);
    for (int i = 0; i < NCO; i++) {
        const float tnext = (i < 63) ? TV(i + 1) : tcur;
        const float td    = (i < 63) ? (tnext - tcur) : 1e10f;
        const float dd    = g_sig_c[b * NCO + i] * td * nrm;
        const float T     = __expf(-S);
        const float alpha = 1.0f - __expf(-dd);
        const float wi    = alpha * T;
        S += dd;
        w[i] = wi;
        acc += wi;
        depth = fmaf(wi, tcur, depth);
        wt0   = fmaf(wi, TV0(i), wt0);
        const float* rp = &g_rgb_c[(size_t)(b * NCO + i) * 3];
        c0 = fmaf(wi, rp[0], c0);
        c1 = fmaf(wi, rp[1], c1);
        c2 = fmaf(wi, rp[2], c2);
        tcur = tnext;
    }
    float* ob = out + (size_t)b * 16;
    ob[0] = c0 + bkgd[0] * (1.0f - acc);
    ob[1] = c1 + bkgd[1] * (1.0f - acc);
    ob[2] = c2 + bkgd[2] * (1.0f - acc);
    ob[3] = depth;
    ob[4] = acc;
    ob[5] = acc * o0x + wt0 * d0x;
    ob[6] = acc * o0y + wt0 * d0y;
    ob[7] = acc * o0z + wt0 * d0z;

    float ws = 0.f;
    for (int k = 1; k <= 62; k++) ws += w[k];
    const float pad = fmaxf(1e-5f - ws, 0.0f);
    const float add = pad * (1.0f / 62.0f);
    ws += pad;
    const float inv = 1.0f / ws;
    float cdf[64];
    cdf[0] = 0.0f;
    float cs = 0.f;
    for (int k = 1; k <= 61; k++) {
        cs += (w[k] + add) * inv;
        cdf[k] = fminf(cs, 1.0f);
    }
    cdf[62] = 1.0f;

    auto BIN = [&](int k) -> float { return 0.5f * (TV(k) + TV(k + 1)); };

    const float ueps = 1.1920929e-07f;
    const float du = (1.0f - ueps) * (1.0f / 127.0f);
    int idx = 0, ti = 0, p = 0;
    const size_t base = (size_t)b * NSF;
    for (int s = 0; s < NFI; s++) {
        const float u = (s == 127) ? (1.0f - ueps) : (float)s * du;
        while (idx < 61 && cdf[idx + 1] <= u) idx++;
        const float gg0 = cdf[idx], gg1 = cdf[idx + 1];
        float tt = (u - gg0) / (gg1 - gg0);
        if (!(tt == tt)) tt = 0.0f;
        tt = fminf(fmaxf(tt, 0.0f), 1.0f);
        const float bb0 = BIN(idx);
        const float z = fmaf(tt, BIN(idx + 1) - bb0, bb0);
        while (ti < NCO && TV(ti) <= z) { g_z[base + p] = TV(ti); p++; ti++; }
        g_z[base + p] = z; p++;
    }
    while (ti < NCO) { g_z[base + p] = TV(ti); p++; ti++; }
}

// ---------------- fine render (R3 scalar, verbatim) ----------------
__global__ void fine_render_kernel(
    const float* __restrict__ org, const float* __restrict__ dirv,
    const float* __restrict__ bkgd, float* __restrict__ out)
{
    const int b = blockIdx.x * blockDim.x + threadIdx.x;
    if (b >= BATCH) return;

    const float dxx = dirv[3*b+0], dyy = dirv[3*b+1], dzz = dirv[3*b+2];
    const float nrm = sqrtf(dxx*dxx + dyy*dyy + dzz*dzz);
    const float o0x = org[0],  o0y = org[1],  o0z = org[2];
    const float d0x = dirv[0], d0y = dirv[1], d0z = dirv[2];

    const float* zr = g_z + (size_t)b * NSF;
    float S = 0.f, acc = 0.f, depth = 0.f, wz0 = 0.f, c0 = 0.f, c1 = 0.f, c2 = 0.f;
    float zc = zr[0];
    for (int i = 0; i < NSF; i++) {
        const float znext = (i < NSF - 1) ? zr[i + 1] : zc;
        const float td    = (i < NSF - 1) ? (znext - zc) : 1e10f;
        const float dd    = g_sig_f[(size_t)b * NSF + i] * td * nrm;
        const float T     = __expf(-S);
        const float alpha = 1.0f - __expf(-dd);
        const float wi    = alpha * T;
        S += dd;
        acc += wi;
        depth = fmaf(wi, zc, depth);
        wz0   = fmaf(wi, g_z[i], wz0);
        const float* rp = &g_rgb_f[((size_t)b * NSF + i) * 3];
        c0 = fmaf(wi, rp[0], c0);
        c1 = fmaf(wi, rp[1], c1);
        c2 = fmaf(wi, rp[2], c2);
        zc = znext;
    }
    float* ob = out + (size_t)b * 16;
    ob[8]  = c0 + bkgd[0] * (1.0f - acc);
    ob[9]  = c1 + bkgd[1] * (1.0f - acc);
    ob[10] = c2 + bkgd[2] * (1.0f - acc);
    ob[11] = depth;
    ob[12] = acc;
    ob[13] = acc * o0x + wz0 * d0x;
    ob[14] = acc * o0y + wz0 * d0y;
    ob[15] = acc * o0z + wz0 * d0z;
}

// ---------------- launch ----------------
extern "C" void kernel_launch(void* const* d_in, const int* in_sizes, int n_in,
                              void* d_out, int out_size)
{
    const float* org   = (const float*)d_in[0];
    const float* dirv  = (const float*)d_in[1];
    const float* nearp = (const float*)d_in[2];
    const float* farp  = (const float*)d_in[3];
    const float* bkgd  = (const float*)d_in[4];

    const float* w1c = (const float*)d_in[5];
    const float* b1c = (const float*)d_in[6];
    const float* w2c = (const float*)d_in[7];
    const float* b2c = (const float*)d_in[8];
    const float* wrc = (const float*)d_in[9];
    const float* brc = (const float*)d_in[10];
    const float* wdc = (const float*)d_in[11];
    const float* bdc = (const float*)d_in[12];

    const float* w1f = (const float*)d_in[13];
    const float* b1f = (const float*)d_in[14];
    const float* w2f = (const float*)d_in[15];
    const float* b2f = (const float*)d_in[16];
    const float* wrf = (const float*)d_in[17];
    const float* brf = (const float*)d_in[18];
    const float* wdf = (const float*)d_in[19];
    const float* bdf = (const float*)d_in[20];

    float* out = (float*)d_out;

    // coarse: 16384*64/16 = 65536 tiles; 4 warps * 8 tiles per block -> 2048 blocks
    mlp_mma_kernel<NCO, true, 8><<<2048, 128>>>(
        org, dirv, nearp, farp, w1c, b1c, w2c, b2c, wrc, brc, wdc, bdc);

    coarse_post_kernel<<<BATCH / 32, 32>>>(org, dirv, nearp, farp, bkgd, out);

    // fine: 16384*192/16 = 196608 tiles -> 6144 blocks
    mlp_mma_kernel<NSF, false, 8><<<6144, 128>>>(
        org, dirv, nearp, farp, w1f, b1f, w2f, b2f, wrf, brf, wdf, bdf);

    fine_render_kernel<<<BATCH / 32, 32>>>(org, dirv, bkgd, out);
}

// round 6
// speedup vs baseline: 2.4434x; 1.0008x over previous
#include <cuda_runtime.h>
#include <math.h>

#define BATCH 16384
#define NCO   64
#define NFI   128
#define NSF   192
#define HID   64

// ---------------- scratch (device globals; no allocation allowed) ----------------
__device__ float g_rgb_c[BATCH * NCO * 3];
__device__ float g_sig_c[BATCH * NCO];
__device__ float g_z    [BATCH * NSF];
__device__ float g_rgb_f[BATCH * NSF * 3];
__device__ float g_sig_f[BATCH * NSF];

__device__ __forceinline__ float sigmoidf_(float z) { return 1.0f / (1.0f + __expf(-z)); }

__device__ __forceinline__ unsigned tf32_rna(float v) {
    unsigned r; asm("cvt.rna.tf32.f32 %0, %1;" : "=r"(r) : "f"(v)); return r;
}
__device__ __forceinline__ void mma_tf32(float& c0, float& c1, float& c2, float& c3,
    unsigned a0, unsigned a1, unsigned a2, unsigned a3, unsigned b0, unsigned b1) {
    asm("mma.sync.aligned.m16n8k8.row.col.f32.tf32.tf32.f32 "
        "{%0,%1,%2,%3},{%4,%5,%6,%7},{%8,%9},{%0,%1,%2,%3};"
        : "+f"(c0), "+f"(c1), "+f"(c2), "+f"(c3)
        : "r"(a0), "r"(a1), "r"(a2), "r"(a3), "r"(b0), "r"(b1));
}

// ---------------- MLP via mma.sync tf32 (3xTF32), warp per 16-sample tile ----------------
// B fragments precomputed per block into a fragment-ordered table:
// sFragB[(nc*8+kc)*32 + lane] = {bh0, bh1, bl0, bl1}  -> one LDS.128 per (nc,kc).
template <int NS, bool COARSE, int TPW>
__global__ void __launch_bounds__(128) mlp_mma_kernel(
    const float* __restrict__ org,  const float* __restrict__ dirv,
    const float* __restrict__ nearp,const float* __restrict__ farp,
    const float* __restrict__ w1,   const float* __restrict__ b1,
    const float* __restrict__ w2,   const float* __restrict__ b2,
    const float* __restrict__ wr,   const float* __restrict__ br,
    const float* __restrict__ wd,   const float* __restrict__ bd)
{
    __shared__ __align__(16) uint4 sFragB[64 * 32];      // 32 KB
    __shared__ __align__(16) float sL1[HID * 4];         // (w1_0, w1_1, w1_2, b1)
    __shared__ __align__(16) float sHD[HID * 4];         // (wr0, wr1, wr2, wd)
    __shared__ float sB2[HID];
    __shared__ float sBh[4];

    const int tid = threadIdx.x;
    // build fragment table: entry e -> pair (nc,kc) = e>>5, lane lv = e&31
    for (int e = tid; e < 64 * 32; e += 128) {
        const int pair = e >> 5, lv = e & 31;
        const int nc = pair >> 3, kc = pair & 7;
        const int gv = lv >> 2, tv = lv & 3;
        const int kr = kc * 8 + tv;
        const int nB = nc * 8 + gv;
        const float v0 = w2[kr * HID + nB];
        const float v1 = w2[(kr + 4) * HID + nB];
        const unsigned h0 = tf32_rna(v0);
        const unsigned h1 = tf32_rna(v1);
        const unsigned l0 = tf32_rna(v0 - __uint_as_float(h0));
        const unsigned l1 = tf32_rna(v1 - __uint_as_float(h1));
        sFragB[e] = make_uint4(h0, h1, l0, l1);
    }
    for (int i = tid; i < HID; i += 128) {
        sL1[4*i+0] = w1[i]; sL1[4*i+1] = w1[64+i]; sL1[4*i+2] = w1[128+i]; sL1[4*i+3] = b1[i];
        sHD[4*i+0] = wr[3*i]; sHD[4*i+1] = wr[3*i+1]; sHD[4*i+2] = wr[3*i+2]; sHD[4*i+3] = wd[i];
        sB2[i] = b2[i];
    }
    if (tid == 0) { sBh[0] = br[0]; sBh[1] = br[1]; sBh[2] = br[2]; sBh[3] = bd[0]; }
    __syncthreads();

    const int lane = tid & 31;
    const int gid  = lane >> 2;   // 0..7 : sample rows gid, gid+8
    const int tig  = lane & 3;    // 0..3
    const int warpGlobal = blockIdx.x * 4 + (tid >> 5);

#pragma unroll 1
    for (int it = 0; it < TPW; ++it) {
        const int tileIdx = warpGlobal * TPW + it;
        const int s0 = tileIdx * 16;
        const int b  = s0 / NS;                 // 16 | NS -> tile within one ray

        const float ox = org[3*b], oy = org[3*b+1], oz = org[3*b+2];
        const float dx = dirv[3*b], dy = dirv[3*b+1], dz = dirv[3*b+2];
        float t0, t1;
        if (COARSE) {
            const float nb = nearp[b], fb = farp[b];
            const int i0 = (s0 % NS) + gid, i1 = i0 + 8;
            float q0 = (i0 == 63) ? 1.0f : (float)i0 * (1.0f / 63.0f);
            float q1 = (i1 == 63) ? 1.0f : (float)i1 * (1.0f / 63.0f);
            t0 = nb * (1.0f - q0) + fb * q0;
            t1 = nb * (1.0f - q1) + fb * q1;
        } else {
            t0 = g_z[s0 + gid];
            t1 = g_z[s0 + gid + 8];
        }
        const float x00 = fmaf(t0, dx, ox), x01 = fmaf(t0, dy, oy), x02 = fmaf(t0, dz, oz);
        const float x10 = fmaf(t1, dx, ox), x11 = fmaf(t1, dy, oy), x12 = fmaf(t1, dz, oz);

        // ---- layer 1 (scalar fp32) straight into A fragments (hi/lo tf32 split) ----
        unsigned Ahi0[16], Alo0[16], Ahi1[16], Alo1[16];
#pragma unroll
        for (int m = 0; m < 16; m++) {
            const int c = 4 * m + tig;
            const float4 L = *(const float4*)&sL1[4 * c];
            const float hA = fmaxf(fmaf(x02, L.z, fmaf(x01, L.y, fmaf(x00, L.x, L.w))), 0.0f);
            const float hB = fmaxf(fmaf(x12, L.z, fmaf(x11, L.y, fmaf(x10, L.x, L.w))), 0.0f);
            const unsigned ha = tf32_rna(hA);
            Ahi0[m] = ha; Alo0[m] = tf32_rna(hA - __uint_as_float(ha));
            const unsigned hb = tf32_rna(hB);
            Ahi1[m] = hb; Alo1[m] = tf32_rna(hB - __uint_as_float(hb));
        }

        // ---- layer 2 via mma (3xTF32) + streamed heads ----
        float hp0[4] = {0.f, 0.f, 0.f, 0.f};
        float hp1[4] = {0.f, 0.f, 0.f, 0.f};
#pragma unroll 1
        for (int nc = 0; nc < 8; nc++) {
            const int j0 = nc * 8 + 2 * tig;
            float c0 = sB2[j0], c1 = sB2[j0 + 1];
            float c2 = c0, c3 = c1;
            const uint4* frag = &sFragB[(nc * 8) * 32 + lane];
#pragma unroll
            for (int kc = 0; kc < 8; kc++) {
                const uint4 f = frag[kc * 32];
                mma_tf32(c0, c1, c2, c3,
                         Ahi0[2*kc], Ahi1[2*kc], Ahi0[2*kc+1], Ahi1[2*kc+1], f.x, f.y);
                mma_tf32(c0, c1, c2, c3,
                         Alo0[2*kc], Alo1[2*kc], Alo0[2*kc+1], Alo1[2*kc+1], f.x, f.y);
                mma_tf32(c0, c1, c2, c3,
                         Ahi0[2*kc], Ahi1[2*kc], Ahi0[2*kc+1], Ahi1[2*kc+1], f.z, f.w);
            }
            const float4 H0 = *(const float4*)&sHD[4 * j0];
            const float4 H1 = *(const float4*)&sHD[4 * (j0 + 1)];
            const float v00 = fmaxf(c0, 0.f), v01 = fmaxf(c1, 0.f);
            const float v10 = fmaxf(c2, 0.f), v11 = fmaxf(c3, 0.f);
            hp0[0] = fmaf(v00, H0.x, fmaf(v01, H1.x, hp0[0]));
            hp0[1] = fmaf(v00, H0.y, fmaf(v01, H1.y, hp0[1]));
            hp0[2] = fmaf(v00, H0.z, fmaf(v01, H1.z, hp0[2]));
            hp0[3] = fmaf(v00, H0.w, fmaf(v01, H1.w, hp0[3]));
            hp1[0] = fmaf(v10, H0.x, fmaf(v11, H1.x, hp1[0]));
            hp1[1] = fmaf(v10, H0.y, fmaf(v11, H1.y, hp1[1]));
            hp1[2] = fmaf(v10, H0.z, fmaf(v11, H1.z, hp1[2]));
            hp1[3] = fmaf(v10, H0.w, fmaf(v11, H1.w, hp1[3]));
        }

#pragma unroll
        for (int c = 0; c < 4; c++) {
            hp0[c] += __shfl_xor_sync(0xffffffffu, hp0[c], 1);
            hp0[c] += __shfl_xor_sync(0xffffffffu, hp0[c], 2);
            hp1[c] += __shfl_xor_sync(0xffffffffu, hp1[c], 1);
            hp1[c] += __shfl_xor_sync(0xffffffffu, hp1[c], 2);
        }
        if (tig == 0) {
            float* rgb = COARSE ? g_rgb_c : g_rgb_f;
            float* sg  = COARSE ? g_sig_c : g_sig_f;
            const int sA = s0 + gid, sB = s0 + gid + 8;
            rgb[3*sA+0] = sigmoidf_(hp0[0] + sBh[0]);
            rgb[3*sA+1] = sigmoidf_(hp0[1] + sBh[1]);
            rgb[3*sA+2] = sigmoidf_(hp0[2] + sBh[2]);
            sg[sA] = fmaxf(hp0[3] + sBh[3], 0.f);
            rgb[3*sB+0] = sigmoidf_(hp1[0] + sBh[0]);
            rgb[3*sB+1] = sigmoidf_(hp1[1] + sBh[1]);
            rgb[3*sB+2] = sigmoidf_(hp1[2] + sBh[2]);
            sg[sB] = fmaxf(hp1[3] + sBh[3], 0.f);
        }
    }
}

// ---------------- coarse render + inverse-CDF sampling + sorted merge (validated scalar) ----------------
__global__ void coarse_post_kernel(
    const float* __restrict__ org, const float* __restrict__ dirv,
    const float* __restrict__ nearp, const float* __restrict__ farp,
    const float* __restrict__ bkgd, float* __restrict__ out)
{
    const int b = blockIdx.x * blockDim.x + threadIdx.x;
    if (b >= BATCH) return;

    const float nb = nearp[b], fb = farp[b];
    const float n0 = nearp[0], f0 = farp[0];
    const float dxx = dirv[3*b+0], dyy = dirv[3*b+1], dzz = dirv[3*b+2];
    const float nrm = sqrtf(dxx*dxx + dyy*dyy + dzz*dzz);
    const float o0x = org[0],  o0y = org[1],  o0z = org[2];
    const float d0x = dirv[0], d0y = dirv[1], d0z = dirv[2];

    auto TV  = [&](int i) -> float {
        float tq = (i == 63) ? 1.0f : (float)i * (1.0f / 63.0f);
        return nb * (1.0f - tq) + fb * tq;
    };
    auto TV0 = [&](int i) -> float {
        float tq = (i == 63) ? 1.0f : (float)i * (1.0f / 63.0f);
        return n0 * (1.0f - tq) + f0 * tq;
    };

    float w[NCO];
    float S = 0.f, acc = 0.f, depth = 0.f, wt0 = 0.f, c0 = 0.f, c1 = 0.f, c2 = 0.f;
    float tcur = TV(0);
    for (int i = 0; i < NCO; i++) {
        const float tnext = (i < 63) ? TV(i + 1) : tcur;
        const float td    = (i < 63) ? (tnext - tcur) : 1e10f;
        const float dd    = g_sig_c[b * NCO + i] * td * nrm;
        const float T     = __expf(-S);
        const float alpha = 1.0f - __expf(-dd);
        const float wi    = alpha * T;
        S += dd;
        w[i] = wi;
        acc += wi;
        depth = fmaf(wi, tcur, depth);
        wt0   = fmaf(wi, TV0(i), wt0);
        const float* rp = &g_rgb_c[(size_t)(b * NCO + i) * 3];
        c0 = fmaf(wi, rp[0], c0);
        c1 = fmaf(wi, rp[1], c1);
        c2 = fmaf(wi, rp[2], c2);
        tcur = tnext;
    }
    float* ob = out + (size_t)b * 16;
    ob[0] = c0 + bkgd[0] * (1.0f - acc);
    ob[1] = c1 + bkgd[1] * (1.0f - acc);
    ob[2] = c2 + bkgd[2] * (1.0f - acc);
    ob[3] = depth;
    ob[4] = acc;
    ob[5] = acc * o0x + wt0 * d0x;
    ob[6] = acc * o0y + wt0 * d0y;
    ob[7] = acc * o0z + wt0 * d0z;

    float ws = 0.f;
    for (int k = 1; k <= 62; k++) ws += w[k];
    const float pad = fmaxf(1e-5f - ws, 0.0f);
    const float add = pad * (1.0f / 62.0f);
    ws += pad;
    const float inv = 1.0f / ws;
    float cdf[64];
    cdf[0] = 0.0f;
    float cs = 0.f;
    for (int k = 1; k <= 61; k++) {
        cs += (w[k] + add) * inv;
        cdf[k] = fminf(cs, 1.0f);
    }
    cdf[62] = 1.0f;

    auto BIN = [&](int k) -> float { return 0.5f * (TV(k) + TV(k + 1)); };

    const float ueps = 1.1920929e-07f;
    const float du = (1.0f - ueps) * (1.0f / 127.0f);
    int idx = 0, ti = 0, p = 0;
    const size_t base = (size_t)b * NSF;
    for (int s = 0; s < NFI; s++) {
        const float u = (s == 127) ? (1.0f - ueps) : (float)s * du;
        while (idx < 61 && cdf[idx + 1] <= u) idx++;
        const float gg0 = cdf[idx], gg1 = cdf[idx + 1];
        float tt = (u - gg0) / (gg1 - gg0);
        if (!(tt == tt)) tt = 0.0f;
        tt = fminf(fmaxf(tt, 0.0f), 1.0f);
        const float bb0 = BIN(idx);
        const float z = fmaf(tt, BIN(idx + 1) - bb0, bb0);
        while (ti < NCO && TV(ti) <= z) { g_z[base + p] = TV(ti); p++; ti++; }
        g_z[base + p] = z; p++;
    }
    while (ti < NCO) { g_z[base + p] = TV(ti); p++; ti++; }
}

// ---------------- fine render (validated scalar) ----------------
__global__ void fine_render_kernel(
    const float* __restrict__ org, const float* __restrict__ dirv,
    const float* __restrict__ bkgd, float* __restrict__ out)
{
    const int b = blockIdx.x * blockDim.x + threadIdx.x;
    if (b >= BATCH) return;

    const float dxx = dirv[3*b+0], dyy = dirv[3*b+1], dzz = dirv[3*b+2];
    const float nrm = sqrtf(dxx*dxx + dyy*dyy + dzz*dzz);
    const float o0x = org[0],  o0y = org[1],  o0z = org[2];
    const float d0x = dirv[0], d0y = dirv[1], d0z = dirv[2];

    const float* zr = g_z + (size_t)b * NSF;
    float S = 0.f, acc = 0.f, depth = 0.f, wz0 = 0.f, c0 = 0.f, c1 = 0.f, c2 = 0.f;
    float zc = zr[0];
    for (int i = 0; i < NSF; i++) {
        const float znext = (i < NSF - 1) ? zr[i + 1] : zc;
        const float td    = (i < NSF - 1) ? (znext - zc) : 1e10f;
        const float dd    = g_sig_f[(size_t)b * NSF + i] * td * nrm;
        const float T     = __expf(-S);
        const float alpha = 1.0f - __expf(-dd);
        const float wi    = alpha * T;
        S += dd;
        acc += wi;
        depth = fmaf(wi, zc, depth);
        wz0   = fmaf(wi, g_z[i], wz0);
        const float* rp = &g_rgb_f[((size_t)b * NSF + i) * 3];
        c0 = fmaf(wi, rp[0], c0);
        c1 = fmaf(wi, rp[1], c1);
        c2 = fmaf(wi, rp[2], c2);
        zc = znext;
    }
    float* ob = out + (size_t)b * 16;
    ob[8]  = c0 + bkgd[0] * (1.0f - acc);
    ob[9]  = c1 + bkgd[1] * (1.0f - acc);
    ob[10] = c2 + bkgd[2] * (1.0f - acc);
    ob[11] = depth;
    ob[12] = acc;
    ob[13] = acc * o0x + wz0 * d0x;
    ob[14] = acc * o0y + wz0 * d0y;
    ob[15] = acc * o0z + wz0 * d0z;
}

// ---------------- launch ----------------
extern "C" void kernel_launch(void* const* d_in, const int* in_sizes, int n_in,
                              void* d_out, int out_size)
{
    const float* org   = (const float*)d_in[0];
    const float* dirv  = (const float*)d_in[1];
    const float* nearp = (const float*)d_in[2];
    const float* farp  = (const float*)d_in[3];
    const float* bkgd  = (const float*)d_in[4];

    const float* w1c = (const float*)d_in[5];
    const float* b1c = (const float*)d_in[6];
    const float* w2c = (const float*)d_in[7];
    const float* b2c = (const float*)d_in[8];
    const float* wrc = (const float*)d_in[9];
    const float* brc = (const float*)d_in[10];
    const float* wdc = (const float*)d_in[11];
    const float* bdc = (const float*)d_in[12];

    const float* w1f = (const float*)d_in[13];
    const float* b1f = (const float*)d_in[14];
    const float* w2f = (const float*)d_in[15];
    const float* b2f = (const float*)d_in[16];
    const float* wrf = (const float*)d_in[17];
    const float* brf = (const float*)d_in[18];
    const float* wdf = (const float*)d_in[19];
    const float* bdf = (const float*)d_in[20];

    float* out = (float*)d_out;

    // coarse: 16384*64/16 = 65536 tiles; 4 warps * 8 tiles per block -> 2048 blocks
    mlp_mma_kernel<NCO, true, 8><<<2048, 128>>>(
        org, dirv, nearp, farp, w1c, b1c, w2c, b2c, wrc, brc, wdc, bdc);

    coarse_post_kernel<<<BATCH / 32, 32>>>(org, dirv, nearp, farp, bkgd, out);

    // fine: 16384*192/16 = 196608 tiles -> 6144 blocks
    mlp_mma_kernel<NSF, false, 8><<<6144, 128>>>(
        org, dirv, nearp, farp, w1f, b1f, w2f, b2f, wrf, brf, wdf, bdf);

    fine_render_kernel<<<BATCH / 32, 32>>>(org, dirv, bkgd, out);
}

// round 7
// speedup vs baseline: 3.3520x; 1.3718x over previous
#include <cuda_runtime.h>
#include <cuda_fp16.h>
#include <math.h>

#define BATCH 16384
#define NCO   64
#define NFI   128
#define NSF   192
#define HID   64

// ---------------- scratch (device globals; no allocation allowed) ----------------
__device__ float g_rgb_c[BATCH * NCO * 3];
__device__ float g_sig_c[BATCH * NCO];
__device__ float g_z    [BATCH * NSF];
__device__ float g_rgb_f[BATCH * NSF * 3];
__device__ float g_sig_f[BATCH * NSF];

__device__ __forceinline__ float sigmoidf_(float z) { return 1.0f / (1.0f + __expf(-z)); }

// split fp32 into fp16 hi + fp16 lo (hi+lo carries ~22 mantissa bits)
__device__ __forceinline__ void split_h(float v, unsigned short& hi, unsigned short& lo) {
    const __half h = __float2half_rn(v);
    hi = __half_as_ushort(h);
    lo = __half_as_ushort(__float2half_rn(v - __half2float(h)));
}
__device__ __forceinline__ unsigned pack2(unsigned short l, unsigned short h) {
    return (unsigned)l | ((unsigned)h << 16);
}

__device__ __forceinline__ void mma_f16(float& c0, float& c1, float& c2, float& c3,
    unsigned a0, unsigned a1, unsigned a2, unsigned a3, unsigned b0, unsigned b1) {
    asm("mma.sync.aligned.m16n8k16.row.col.f32.f16.f16.f32 "
        "{%0,%1,%2,%3},{%4,%5,%6,%7},{%8,%9},{%0,%1,%2,%3};"
        : "+f"(c0), "+f"(c1), "+f"(c2), "+f"(c3)
        : "r"(a0), "r"(a1), "r"(a2), "r"(a3), "r"(b0), "r"(b1));
}

// ---------------- MLP via mma.sync f16 (hi/lo split), warp per 16-sample tile ----------------
// B fragments precomputed per block, fragment-ordered:
// sFragB[(nc*4+kc)*32 + lane] = {bh0, bh1, bl0, bl1} (packed half2 each).
template <int NS, bool COARSE, int TPW>
__global__ void __launch_bounds__(128) mlp_mma_kernel(
    const float* __restrict__ org,  const float* __restrict__ dirv,
    const float* __restrict__ nearp,const float* __restrict__ farp,
    const float* __restrict__ w1,   const float* __restrict__ b1,
    const float* __restrict__ w2,   const float* __restrict__ b2,
    const float* __restrict__ wr,   const float* __restrict__ br,
    const float* __restrict__ wd,   const float* __restrict__ bd)
{
    __shared__ __align__(16) uint4 sFragB[32 * 32];      // 16 KB
    __shared__ __align__(16) float sL1[HID * 4];         // (w1_0, w1_1, w1_2, b1)
    __shared__ __align__(16) float sHD[HID * 4];         // (wr0, wr1, wr2, wd)
    __shared__ float sB2[HID];
    __shared__ float sBh[4];

    const int tid = threadIdx.x;
    // build fragment table: entry e -> (nc,kc) = e>>5, lane lv = e&31
    for (int e = tid; e < 32 * 32; e += 128) {
        const int pair = e >> 5, lv = e & 31;
        const int nc = pair >> 2, kc = pair & 3;
        const int gv = lv >> 2, tv = lv & 3;
        const int n  = nc * 8 + gv;
        const int k0 = 16 * kc + 2 * tv;       // b0 covers k0, k0+1
        const int k2 = k0 + 8;                 // b1 covers k2, k2+1
        unsigned short h00, l00, h01, l01, h20, l20, h21, l21;
        split_h(w2[(k0    ) * HID + n], h00, l00);
        split_h(w2[(k0 + 1) * HID + n], h01, l01);
        split_h(w2[(k2    ) * HID + n], h20, l20);
        split_h(w2[(k2 + 1) * HID + n], h21, l21);
        sFragB[e] = make_uint4(pack2(h00, h01), pack2(h20, h21),
                               pack2(l00, l01), pack2(l20, l21));
    }
    for (int i = tid; i < HID; i += 128) {
        sL1[4*i+0] = w1[i]; sL1[4*i+1] = w1[64+i]; sL1[4*i+2] = w1[128+i]; sL1[4*i+3] = b1[i];
        sHD[4*i+0] = wr[3*i]; sHD[4*i+1] = wr[3*i+1]; sHD[4*i+2] = wr[3*i+2]; sHD[4*i+3] = wd[i];
        sB2[i] = b2[i];
    }
    if (tid == 0) { sBh[0] = br[0]; sBh[1] = br[1]; sBh[2] = br[2]; sBh[3] = bd[0]; }
    __syncthreads();

    const int lane = tid & 31;
    const int gid  = lane >> 2;   // 0..7 : sample rows gid, gid+8
    const int tig  = lane & 3;    // 0..3
    const int warpGlobal = blockIdx.x * 4 + (tid >> 5);

#pragma unroll 1
    for (int it = 0; it < TPW; ++it) {
        const int tileIdx = warpGlobal * TPW + it;
        const int s0 = tileIdx * 16;
        const int b  = s0 / NS;                 // 16 | NS -> tile within one ray

        const float ox = org[3*b], oy = org[3*b+1], oz = org[3*b+2];
        const float dx = dirv[3*b], dy = dirv[3*b+1], dz = dirv[3*b+2];
        float t0, t1;
        if (COARSE) {
            const float nb = nearp[b], fb = farp[b];
            const int i0 = (s0 % NS) + gid, i1 = i0 + 8;
            float q0 = (i0 == 63) ? 1.0f : (float)i0 * (1.0f / 63.0f);
            float q1 = (i1 == 63) ? 1.0f : (float)i1 * (1.0f / 63.0f);
            t0 = nb * (1.0f - q0) + fb * q0;
            t1 = nb * (1.0f - q1) + fb * q1;
        } else {
            t0 = g_z[s0 + gid];
            t1 = g_z[s0 + gid + 8];
        }
        const float x00 = fmaf(t0, dx, ox), x01 = fmaf(t0, dy, oy), x02 = fmaf(t0, dz, oz);
        const float x10 = fmaf(t1, dx, ox), x11 = fmaf(t1, dy, oy), x12 = fmaf(t1, dz, oz);

        // ---- layer 1 (scalar fp32) straight into fp16 A fragments (hi/lo split) ----
        // per kc: lane owns cols {2tig, 2tig+1, 2tig+8, 2tig+9} + 16*kc, rows gid & gid+8.
        unsigned Ah[4][4], Al[4][4];
#pragma unroll
        for (int kc = 0; kc < 4; kc++) {
            unsigned short hg[4], lg[4], hG[4], lG[4];
#pragma unroll
            for (int q = 0; q < 4; q++) {
                const int c = 16 * kc + ((q >> 1) << 3) + 2 * tig + (q & 1);
                const float4 L = *(const float4*)&sL1[4 * c];
                const float hA = fmaxf(fmaf(x02, L.z, fmaf(x01, L.y, fmaf(x00, L.x, L.w))), 0.0f);
                const float hB = fmaxf(fmaf(x12, L.z, fmaf(x11, L.y, fmaf(x10, L.x, L.w))), 0.0f);
                split_h(hA, hg[q], lg[q]);
                split_h(hB, hG[q], lG[q]);
            }
            Ah[kc][0] = pack2(hg[0], hg[1]); Ah[kc][1] = pack2(hG[0], hG[1]);
            Ah[kc][2] = pack2(hg[2], hg[3]); Ah[kc][3] = pack2(hG[2], hG[3]);
            Al[kc][0] = pack2(lg[0], lg[1]); Al[kc][1] = pack2(lG[0], lG[1]);
            Al[kc][2] = pack2(lg[2], lg[3]); Al[kc][3] = pack2(lG[2], lG[3]);
        }

        // ---- layer 2 via mma (AhBh + AlBh + AhBl) + streamed heads ----
        float hp0[4] = {0.f, 0.f, 0.f, 0.f};
        float hp1[4] = {0.f, 0.f, 0.f, 0.f};
#pragma unroll 1
        for (int nc = 0; nc < 8; nc++) {
            const int j0 = nc * 8 + 2 * tig;
            float c0 = sB2[j0], c1 = sB2[j0 + 1];
            float c2 = c0, c3 = c1;
            const uint4* frag = &sFragB[(nc * 4) * 32 + lane];
#pragma unroll
            for (int kc = 0; kc < 4; kc++) {
                const uint4 f = frag[kc * 32];
                mma_f16(c0, c1, c2, c3,
                        Ah[kc][0], Ah[kc][1], Ah[kc][2], Ah[kc][3], f.x, f.y);
                mma_f16(c0, c1, c2, c3,
                        Al[kc][0], Al[kc][1], Al[kc][2], Al[kc][3], f.x, f.y);
                mma_f16(c0, c1, c2, c3,
                        Ah[kc][0], Ah[kc][1], Ah[kc][2], Ah[kc][3], f.z, f.w);
            }
            const float4 H0 = *(const float4*)&sHD[4 * j0];
            const float4 H1 = *(const float4*)&sHD[4 * (j0 + 1)];
            const float v00 = fmaxf(c0, 0.f), v01 = fmaxf(c1, 0.f);
            const float v10 = fmaxf(c2, 0.f), v11 = fmaxf(c3, 0.f);
            hp0[0] = fmaf(v00, H0.x, fmaf(v01, H1.x, hp0[0]));
            hp0[1] = fmaf(v00, H0.y, fmaf(v01, H1.y, hp0[1]));
            hp0[2] = fmaf(v00, H0.z, fmaf(v01, H1.z, hp0[2]));
            hp0[3] = fmaf(v00, H0.w, fmaf(v01, H1.w, hp0[3]));
            hp1[0] = fmaf(v10, H0.x, fmaf(v11, H1.x, hp1[0]));
            hp1[1] = fmaf(v10, H0.y, fmaf(v11, H1.y, hp1[1]));
            hp1[2] = fmaf(v10, H0.z, fmaf(v11, H1.z, hp1[2]));
            hp1[3] = fmaf(v10, H0.w, fmaf(v11, H1.w, hp1[3]));
        }

#pragma unroll
        for (int c = 0; c < 4; c++) {
            hp0[c] += __shfl_xor_sync(0xffffffffu, hp0[c], 1);
            hp0[c] += __shfl_xor_sync(0xffffffffu, hp0[c], 2);
            hp1[c] += __shfl_xor_sync(0xffffffffu, hp1[c], 1);
            hp1[c] += __shfl_xor_sync(0xffffffffu, hp1[c], 2);
        }
        if (tig == 0) {
            float* rgb = COARSE ? g_rgb_c : g_rgb_f;
            float* sg  = COARSE ? g_sig_c : g_sig_f;
            const int sA = s0 + gid, sB = s0 + gid + 8;
            rgb[3*sA+0] = sigmoidf_(hp0[0] + sBh[0]);
            rgb[3*sA+1] = sigmoidf_(hp0[1] + sBh[1]);
            rgb[3*sA+2] = sigmoidf_(hp0[2] + sBh[2]);
            sg[sA] = fmaxf(hp0[3] + sBh[3], 0.f);
            rgb[3*sB+0] = sigmoidf_(hp1[0] + sBh[0]);
            rgb[3*sB+1] = sigmoidf_(hp1[1] + sBh[1]);
            rgb[3*sB+2] = sigmoidf_(hp1[2] + sBh[2]);
            sg[sB] = fmaxf(hp1[3] + sBh[3], 0.f);
        }
    }
}

// ---------------- coarse render + inverse-CDF sampling + sorted merge (validated scalar) ----------------
__global__ void coarse_post_kernel(
    const float* __restrict__ org, const float* __restrict__ dirv,
    const float* __restrict__ nearp, const float* __restrict__ farp,
    const float* __restrict__ bkgd, float* __restrict__ out)
{
    const int b = blockIdx.x * blockDim.x + threadIdx.x;
    if (b >= BATCH) return;

    const float nb = nearp[b], fb = farp[b];
    const float n0 = nearp[0], f0 = farp[0];
    const float dxx = dirv[3*b+0], dyy = dirv[3*b+1], dzz = dirv[3*b+2];
    const float nrm = sqrtf(dxx*dxx + dyy*dyy + dzz*dzz);
    const float o0x = org[0],  o0y = org[1],  o0z = org[2];
    const float d0x = dirv[0], d0y = dirv[1], d0z = dirv[2];

    auto TV  = [&](int i) -> float {
        float tq = (i == 63) ? 1.0f : (float)i * (1.0f / 63.0f);
        return nb * (1.0f - tq) + fb * tq;
    };
    auto TV0 = [&](int i) -> float {
        float tq = (i == 63) ? 1.0f : (float)i * (1.0f / 63.0f);
        return n0 * (1.0f - tq) + f0 * tq;
    };

    float w[NCO];
    float S = 0.f, acc = 0.f, depth = 0.f, wt0 = 0.f, c0 = 0.f, c1 = 0.f, c2 = 0.f;
    float tcur = TV(0);
    for (int i = 0; i < NCO; i++) {
        const float tnext = (i < 63) ? TV(i + 1) : tcur;
        const float td    = (i < 63) ? (tnext - tcur) : 1e10f;
        const float dd    = g_sig_c[b * NCO + i] * td * nrm;
        const float T     = __expf(-S);
        const float alpha = 1.0f - __expf(-dd);
        const float wi    = alpha * T;
        S += dd;
        w[i] = wi;
        acc += wi;
        depth = fmaf(wi, tcur, depth);
        wt0   = fmaf(wi, TV0(i), wt0);
        const float* rp = &g_rgb_c[(size_t)(b * NCO + i) * 3];
        c0 = fmaf(wi, rp[0], c0);
        c1 = fmaf(wi, rp[1], c1);
        c2 = fmaf(wi, rp[2], c2);
        tcur = tnext;
    }
    float* ob = out + (size_t)b * 16;
    ob[0] = c0 + bkgd[0] * (1.0f - acc);
    ob[1] = c1 + bkgd[1] * (1.0f - acc);
    ob[2] = c2 + bkgd[2] * (1.0f - acc);
    ob[3] = depth;
    ob[4] = acc;
    ob[5] = acc * o0x + wt0 * d0x;
    ob[6] = acc * o0y + wt0 * d0y;
    ob[7] = acc * o0z + wt0 * d0z;

    float ws = 0.f;
    for (int k = 1; k <= 62; k++) ws += w[k];
    const float pad = fmaxf(1e-5f - ws, 0.0f);
    const float add = pad * (1.0f / 62.0f);
    ws += pad;
    const float inv = 1.0f / ws;
    float cdf[64];
    cdf[0] = 0.0f;
    float cs = 0.f;
    for (int k = 1; k <= 61; k++) {
        cs += (w[k] + add) * inv;
        cdf[k] = fminf(cs, 1.0f);
    }
    cdf[62] = 1.0f;

    auto BIN = [&](int k) -> float { return 0.5f * (TV(k) + TV(k + 1)); };

    const float ueps = 1.1920929e-07f;
    const float du = (1.0f - ueps) * (1.0f / 127.0f);
    int idx = 0, ti = 0, p = 0;
    const size_t base = (size_t)b * NSF;
    for (int s = 0; s < NFI; s++) {
        const float u = (s == 127) ? (1.0f - ueps) : (float)s * du;
        while (idx < 61 && cdf[idx + 1] <= u) idx++;
        const float gg0 = cdf[idx], gg1 = cdf[idx + 1];
        float tt = (u - gg0) / (gg1 - gg0);
        if (!(tt == tt)) tt = 0.0f;
        tt = fminf(fmaxf(tt, 0.0f), 1.0f);
        const float bb0 = BIN(idx);
        const float z = fmaf(tt, BIN(idx + 1) - bb0, bb0);
        while (ti < NCO && TV(ti) <= z) { g_z[base + p] = TV(ti); p++; ti++; }
        g_z[base + p] = z; p++;
    }
    while (ti < NCO) { g_z[base + p] = TV(ti); p++; ti++; }
}

// ---------------- fine render (validated scalar) ----------------
__global__ void fine_render_kernel(
    const float* __restrict__ org, const float* __restrict__ dirv,
    const float* __restrict__ bkgd, float* __restrict__ out)
{
    const int b = blockIdx.x * blockDim.x + threadIdx.x;
    if (b >= BATCH) return;

    const float dxx = dirv[3*b+0], dyy = dirv[3*b+1], dzz = dirv[3*b+2];
    const float nrm = sqrtf(dxx*dxx + dyy*dyy + dzz*dzz);
    const float o0x = org[0],  o0y = org[1],  o0z = org[2];
    const float d0x = dirv[0], d0y = dirv[1], d0z = dirv[2];

    const float* zr = g_z + (size_t)b * NSF;
    float S = 0.f, acc = 0.f, depth = 0.f, wz0 = 0.f, c0 = 0.f, c1 = 0.f, c2 = 0.f;
    float zc = zr[0];
    for (int i = 0; i < NSF; i++) {
        const float znext = (i < NSF - 1) ? zr[i + 1] : zc;
        const float td    = (i < NSF - 1) ? (znext - zc) : 1e10f;
        const float dd    = g_sig_f[(size_t)b * NSF + i] * td * nrm;
        const float T     = __expf(-S);
        const float alpha = 1.0f - __expf(-dd);
        const float wi    = alpha * T;
        S += dd;
        acc += wi;
        depth = fmaf(wi, zc, depth);
        wz0   = fmaf(wi, g_z[i], wz0);
        const float* rp = &g_rgb_f[((size_t)b * NSF + i) * 3];
        c0 = fmaf(wi, rp[0], c0);
        c1 = fmaf(wi, rp[1], c1);
        c2 = fmaf(wi, rp[2], c2);
        zc = znext;
    }
    float* ob = out + (size_t)b * 16;
    ob[8]  = c0 + bkgd[0] * (1.0f - acc);
    ob[9]  = c1 + bkgd[1] * (1.0f - acc);
    ob[10] = c2 + bkgd[2] * (1.0f - acc);
    ob[11] = depth;
    ob[12] = acc;
    ob[13] = acc * o0x + wz0 * d0x;
    ob[14] = acc * o0y + wz0 * d0y;
    ob[15] = acc * o0z + wz0 * d0z;
}

// ---------------- launch ----------------
extern "C" void kernel_launch(void* const* d_in, const int* in_sizes, int n_in,
                              void* d_out, int out_size)
{
    const float* org   = (const float*)d_in[0];
    const float* dirv  = (const float*)d_in[1];
    const float* nearp = (const float*)d_in[2];
    const float* farp  = (const float*)d_in[3];
    const float* bkgd  = (const float*)d_in[4];

    const float* w1c = (const float*)d_in[5];
    const float* b1c = (const float*)d_in[6];
    const float* w2c = (const float*)d_in[7];
    const float* b2c = (const float*)d_in[8];
    const float* wrc = (const float*)d_in[9];
    const float* brc = (const float*)d_in[10];
    const float* wdc = (const float*)d_in[11];
    const float* bdc = (const float*)d_in[12];

    const float* w1f = (const float*)d_in[13];
    const float* b1f = (const float*)d_in[14];
    const float* w2f = (const float*)d_in[15];
    const float* b2f = (const float*)d_in[16];
    const float* wrf = (const float*)d_in[17];
    const float* brf = (const float*)d_in[18];
    const float* wdf = (const float*)d_in[19];
    const float* bdf = (const float*)d_in[20];

    float* out = (float*)d_out;

    // coarse: 16384*64/16 = 65536 tiles; 4 warps * 8 tiles per block -> 2048 blocks
    mlp_mma_kernel<NCO, true, 8><<<2048, 128>>>(
        org, dirv, nearp, farp, w1c, b1c, w2c, b2c, wrc, brc, wdc, bdc);

    coarse_post_kernel<<<BATCH / 32, 32>>>(org, dirv, nearp, farp, bkgd, out);

    // fine: 16384*192/16 = 196608 tiles -> 6144 blocks
    mlp_mma_kernel<NSF, false, 8><<<6144, 128>>>(
        org, dirv, nearp, farp, w1f, b1f, w2f, b2f, wrf, brf, wdf, bdf);

    fine_render_kernel<<<BATCH / 32, 32>>>(org, dirv, bkgd, out);
}

// round 11
// speedup vs baseline: 3.7081x; 1.1063x over previous
#include <cuda_runtime.h>
#include <cuda_fp16.h>
#include <math.h>

#define BATCH 16384
#define NCO   64
#define NFI   128
#define NSF   192
#define HID   64

// ---------------- scratch (device globals; no allocation allowed) ----------------
__device__ float g_rgb_c[BATCH * NCO * 3];
__device__ float g_sig_c[BATCH * NCO];
__device__ float g_z    [BATCH * NSF];
__device__ float g_rgb_f[BATCH * NSF * 3];
__device__ float g_sig_f[BATCH * NSF];

__device__ __forceinline__ float sigmoidf_(float z) { return 1.0f / (1.0f + __expf(-z)); }

// split fp32 into fp16 hi + fp16 lo (hi+lo carries ~22 mantissa bits)
__device__ __forceinline__ void split_h(float v, unsigned short& hi, unsigned short& lo) {
    const __half h = __float2half_rn(v);
    hi = __half_as_ushort(h);
    lo = __half_as_ushort(__float2half_rn(v - __half2float(h)));
}
__device__ __forceinline__ unsigned pack2(unsigned short l, unsigned short h) {
    return (unsigned)l | ((unsigned)h << 16);
}

__device__ __forceinline__ void mma_f16(float& c0, float& c1, float& c2, float& c3,
    unsigned a0, unsigned a1, unsigned a2, unsigned a3, unsigned b0, unsigned b1) {
    asm("mma.sync.aligned.m16n8k16.row.col.f32.f16.f16.f32 "
        "{%0,%1,%2,%3},{%4,%5,%6,%7},{%8,%9},{%0,%1,%2,%3};"
        : "+f"(c0), "+f"(c1), "+f"(c2), "+f"(c3)
        : "r"(a0), "r"(a1), "r"(a2), "r"(a3), "r"(b0), "r"(b1));
}

// warp helpers
__device__ __forceinline__ float wred(float v) {
#pragma unroll
    for (int o = 16; o; o >>= 1) v += __shfl_xor_sync(0xffffffffu, v, o);
    return v;
}
__device__ __forceinline__ float wscan_incl(float v) {
    const int lane = threadIdx.x & 31;
    float x = v;
#pragma unroll
    for (int o = 1; o < 32; o <<= 1) {
        float n = __shfl_up_sync(0xffffffffu, x, o);
        if (lane >= o) x += n;
    }
    return x;
}

// ---------------- MLP via mma.sync f16 (3-term split), warp per 16-sample tile (R7) ----------------
template <int NS, bool COARSE, int TPW>
__global__ void __launch_bounds__(128) mlp_mma_kernel(
    const float* __restrict__ org,  const float* __restrict__ dirv,
    const float* __restrict__ nearp,const float* __restrict__ farp,
    const float* __restrict__ w1,   const float* __restrict__ b1,
    const float* __restrict__ w2,   const float* __restrict__ b2,
    const float* __restrict__ wr,   const float* __restrict__ br,
    const float* __restrict__ wd,   const float* __restrict__ bd)
{
    __shared__ __align__(16) uint4 sFragB[32 * 32];      // 16 KB
    __shared__ __align__(16) float sL1[HID * 4];
    __shared__ __align__(16) float sHD[HID * 4];
    __shared__ float sB2[HID];
    __shared__ float sBh[4];

    const int tid = threadIdx.x;
    for (int e = tid; e < 32 * 32; e += 128) {
        const int pair = e >> 5, lv = e & 31;
        const int nc = pair >> 2, kc = pair & 3;
        const int gv = lv >> 2, tv = lv & 3;
        const int n  = nc * 8 + gv;
        const int k0 = 16 * kc + 2 * tv;
        const int k2 = k0 + 8;
        unsigned short h00, l00, h01, l01, h20, l20, h21, l21;
        split_h(w2[(k0    ) * HID + n], h00, l00);
        split_h(w2[(k0 + 1) * HID + n], h01, l01);
        split_h(w2[(k2    ) * HID + n], h20, l20);
        split_h(w2[(k2 + 1) * HID + n], h21, l21);
        sFragB[e] = make_uint4(pack2(h00, h01), pack2(h20, h21),
                               pack2(l00, l01), pack2(l20, l21));
    }
    for (int i = tid; i < HID; i += 128) {
        sL1[4*i+0] = w1[i]; sL1[4*i+1] = w1[64+i]; sL1[4*i+2] = w1[128+i]; sL1[4*i+3] = b1[i];
        sHD[4*i+0] = wr[3*i]; sHD[4*i+1] = wr[3*i+1]; sHD[4*i+2] = wr[3*i+2]; sHD[4*i+3] = wd[i];
        sB2[i] = b2[i];
    }
    if (tid == 0) { sBh[0] = br[0]; sBh[1] = br[1]; sBh[2] = br[2]; sBh[3] = bd[0]; }
    __syncthreads();

    const int lane = tid & 31;
    const int gid  = lane >> 2;
    const int tig  = lane & 3;
    const int warpGlobal = blockIdx.x * 4 + (tid >> 5);

#pragma unroll 1
    for (int it = 0; it < TPW; ++it) {
        const int tileIdx = warpGlobal * TPW + it;
        const int s0 = tileIdx * 16;
        const int b  = s0 / NS;

        const float ox = org[3*b], oy = org[3*b+1], oz = org[3*b+2];
        const float dx = dirv[3*b], dy = dirv[3*b+1], dz = dirv[3*b+2];
        float t0, t1;
        if (COARSE) {
            const float nb = nearp[b], fb = farp[b];
            const int i0 = (s0 % NS) + gid, i1 = i0 + 8;
            float q0 = (i0 == 63) ? 1.0f : (float)i0 * (1.0f / 63.0f);
            float q1 = (i1 == 63) ? 1.0f : (float)i1 * (1.0f / 63.0f);
            t0 = nb * (1.0f - q0) + fb * q0;
            t1 = nb * (1.0f - q1) + fb * q1;
        } else {
            t0 = g_z[s0 + gid];
            t1 = g_z[s0 + gid + 8];
        }
        const float x00 = fmaf(t0, dx, ox), x01 = fmaf(t0, dy, oy), x02 = fmaf(t0, dz, oz);
        const float x10 = fmaf(t1, dx, ox), x11 = fmaf(t1, dy, oy), x12 = fmaf(t1, dz, oz);

        unsigned Ah[4][4], Al[4][4];
#pragma unroll
        for (int kc = 0; kc < 4; kc++) {
            unsigned short hg[4], lg[4], hG[4], lG[4];
#pragma unroll
            for (int q = 0; q < 4; q++) {
                const int c = 16 * kc + ((q >> 1) << 3) + 2 * tig + (q & 1);
                const float4 L = *(const float4*)&sL1[4 * c];
                const float hA = fmaxf(fmaf(x02, L.z, fmaf(x01, L.y, fmaf(x00, L.x, L.w))), 0.0f);
                const float hB = fmaxf(fmaf(x12, L.z, fmaf(x11, L.y, fmaf(x10, L.x, L.w))), 0.0f);
                split_h(hA, hg[q], lg[q]);
                split_h(hB, hG[q], lG[q]);
            }
            Ah[kc][0] = pack2(hg[0], hg[1]); Ah[kc][1] = pack2(hG[0], hG[1]);
            Ah[kc][2] = pack2(hg[2], hg[3]); Ah[kc][3] = pack2(hG[2], hG[3]);
            Al[kc][0] = pack2(lg[0], lg[1]); Al[kc][1] = pack2(lG[0], lG[1]);
            Al[kc][2] = pack2(lg[2], lg[3]); Al[kc][3] = pack2(lG[2], lG[3]);
        }

        float hp0[4] = {0.f, 0.f, 0.f, 0.f};
        float hp1[4] = {0.f, 0.f, 0.f, 0.f};
#pragma unroll 1
        for (int nc = 0; nc < 8; nc++) {
            const int j0 = nc * 8 + 2 * tig;
            float c0 = sB2[j0], c1 = sB2[j0 + 1];
            float c2 = c0, c3 = c1;
            const uint4* frag = &sFragB[(nc * 4) * 32 + lane];
#pragma unroll
            for (int kc = 0; kc < 4; kc++) {
                const uint4 f = frag[kc * 32];
                mma_f16(c0, c1, c2, c3,
                        Ah[kc][0], Ah[kc][1], Ah[kc][2], Ah[kc][3], f.x, f.y);
                mma_f16(c0, c1, c2, c3,
                        Al[kc][0], Al[kc][1], Al[kc][2], Al[kc][3], f.x, f.y);
                mma_f16(c0, c1, c2, c3,
                        Ah[kc][0], Ah[kc][1], Ah[kc][2], Ah[kc][3], f.z, f.w);
            }
            const float4 H0 = *(const float4*)&sHD[4 * j0];
            const float4 H1 = *(const float4*)&sHD[4 * (j0 + 1)];
            const float v00 = fmaxf(c0, 0.f), v01 = fmaxf(c1, 0.f);
            const float v10 = fmaxf(c2, 0.f), v11 = fmaxf(c3, 0.f);
            hp0[0] = fmaf(v00, H0.x, fmaf(v01, H1.x, hp0[0]));
            hp0[1] = fmaf(v00, H0.y, fmaf(v01, H1.y, hp0[1]));
            hp0[2] = fmaf(v00, H0.z, fmaf(v01, H1.z, hp0[2]));
            hp0[3] = fmaf(v00, H0.w, fmaf(v01, H1.w, hp0[3]));
            hp1[0] = fmaf(v10, H0.x, fmaf(v11, H1.x, hp1[0]));
            hp1[1] = fmaf(v10, H0.y, fmaf(v11, H1.y, hp1[1]));
            hp1[2] = fmaf(v10, H0.z, fmaf(v11, H1.z, hp1[2]));
            hp1[3] = fmaf(v10, H0.w, fmaf(v11, H1.w, hp1[3]));
        }

#pragma unroll
        for (int c = 0; c < 4; c++) {
            hp0[c] += __shfl_xor_sync(0xffffffffu, hp0[c], 1);
            hp0[c] += __shfl_xor_sync(0xffffffffu, hp0[c], 2);
            hp1[c] += __shfl_xor_sync(0xffffffffu, hp1[c], 1);
            hp1[c] += __shfl_xor_sync(0xffffffffu, hp1[c], 2);
        }
        if (tig == 0) {
            float* rgb = COARSE ? g_rgb_c : g_rgb_f;
            float* sg  = COARSE ? g_sig_c : g_sig_f;
            const int sA = s0 + gid, sB = s0 + gid + 8;
            rgb[3*sA+0] = sigmoidf_(hp0[0] + sBh[0]);
            rgb[3*sA+1] = sigmoidf_(hp0[1] + sBh[1]);
            rgb[3*sA+2] = sigmoidf_(hp0[2] + sBh[2]);
            sg[sA] = fmaxf(hp0[3] + sBh[3], 0.f);
            rgb[3*sB+0] = sigmoidf_(hp1[0] + sBh[0]);
            rgb[3*sB+1] = sigmoidf_(hp1[1] + sBh[1]);
            rgb[3*sB+2] = sigmoidf_(hp1[2] + sBh[2]);
            sg[sB] = fmaxf(hp1[3] + sBh[3], 0.f);
        }
    }
}

// ---------------- coarse render + inverse-CDF sampling + sorted merge (validated scalar) ----------------
__global__ void coarse_post_kernel(
    const float* __restrict__ org, const float* __restrict__ dirv,
    const float* __restrict__ nearp, const float* __restrict__ farp,
    const float* __restrict__ bkgd, float* __restrict__ out)
{
    const int b = blockIdx.x * blockDim.x + threadIdx.x;
    if (b >= BATCH) return;

    const float nb = nearp[b], fb = farp[b];
    const float n0 = nearp[0], f0 = farp[0];
    const float dxx = dirv[3*b+0], dyy = dirv[3*b+1], dzz = dirv[3*b+2];
    const float nrm = sqrtf(dxx*dxx + dyy*dyy + dzz*dzz);
    const float o0x = org[0],  o0y = org[1],  o0z = org[2];
    const float d0x = dirv[0], d0y = dirv[1], d0z = dirv[2];

    auto TV  = [&](int i) -> float {
        float tq = (i == 63) ? 1.0f : (float)i * (1.0f / 63.0f);
        return nb * (1.0f - tq) + fb * tq;
    };
    auto TV0 = [&](int i) -> float {
        float tq = (i == 63) ? 1.0f : (float)i * (1.0f / 63.0f);
        return n0 * (1.0f - tq) + f0 * tq;
    };

    float w[NCO];
    float S = 0.f, acc = 0.f, depth = 0.f, wt0 = 0.f, c0 = 0.f, c1 = 0.f, c2 = 0.f;
    float tcur = TV(0);
    for (int i = 0; i < NCO; i++) {
        const float tnext = (i < 63) ? TV(i + 1) : tcur;
        const float td    = (i < 63) ? (tnext - tcur) : 1e10f;
        const float dd    = g_sig_c[b * NCO + i] * td * nrm;
        const float T     = __expf(-S);
        const float alpha = 1.0f - __expf(-dd);
        const float wi    = alpha * T;
        S += dd;
        w[i] = wi;
        acc += wi;
        depth = fmaf(wi, tcur, depth);
        wt0   = fmaf(wi, TV0(i), wt0);
        const float* rp = &g_rgb_c[(size_t)(b * NCO + i) * 3];
        c0 = fmaf(wi, rp[0], c0);
        c1 = fmaf(wi, rp[1], c1);
        c2 = fmaf(wi, rp[2], c2);
        tcur = tnext;
    }
    float* ob = out + (size_t)b * 16;
    ob[0] = c0 + bkgd[0] * (1.0f - acc);
    ob[1] = c1 + bkgd[1] * (1.0f - acc);
    ob[2] = c2 + bkgd[2] * (1.0f - acc);
    ob[3] = depth;
    ob[4] = acc;
    ob[5] = acc * o0x + wt0 * d0x;
    ob[6] = acc * o0y + wt0 * d0y;
    ob[7] = acc * o0z + wt0 * d0z;

    float ws = 0.f;
    for (int k = 1; k <= 62; k++) ws += w[k];
    const float pad = fmaxf(1e-5f - ws, 0.0f);
    const float add = pad * (1.0f / 62.0f);
    ws += pad;
    const float inv = 1.0f / ws;
    float cdf[64];
    cdf[0] = 0.0f;
    float cs = 0.f;
    for (int k = 1; k <= 61; k++) {
        cs += (w[k] + add) * inv;
        cdf[k] = fminf(cs, 1.0f);
    }
    cdf[62] = 1.0f;

    auto BIN = [&](int k) -> float { return 0.5f * (TV(k) + TV(k + 1)); };

    const float ueps = 1.1920929e-07f;
    const float du = (1.0f - ueps) * (1.0f / 127.0f);
    int idx = 0, ti = 0, p = 0;
    const size_t base = (size_t)b * NSF;
    for (int s = 0; s < NFI; s++) {
        const float u = (s == 127) ? (1.0f - ueps) : (float)s * du;
        while (idx < 61 && cdf[idx + 1] <= u) idx++;
        const float gg0 = cdf[idx], gg1 = cdf[idx + 1];
        float tt = (u - gg0) / (gg1 - gg0);
        if (!(tt == tt)) tt = 0.0f;
        tt = fminf(fmaxf(tt, 0.0f), 1.0f);
        const float bb0 = BIN(idx);
        const float z = fmaf(tt, BIN(idx + 1) - bb0, bb0);
        while (ti < NCO && TV(ti) <= z) { g_z[base + p] = TV(ti); p++; ti++; }
        g_z[base + p] = z; p++;
    }
    while (ti < NCO) { g_z[base + p] = TV(ti); p++; ti++; }
}

// ---------------- fine render: warp-per-ray (scan excludes last-sample dd) ----------------
__global__ void __launch_bounds__(256) fine_render_kernel(
    const float* __restrict__ org, const float* __restrict__ dirv,
    const float* __restrict__ bkgd, float* __restrict__ out)
{
    const int warp = threadIdx.x >> 5;
    const int lane = threadIdx.x & 31;
    const int b = blockIdx.x * 8 + warp;

    const float dxx = dirv[3*b+0], dyy = dirv[3*b+1], dzz = dirv[3*b+2];
    const float nrm = sqrtf(dxx*dxx + dyy*dyy + dzz*dzz);

    const float* zr = g_z + (size_t)b * NSF;
    const int i0 = 6 * lane;

    float z[7];
#pragma unroll
    for (int r = 0; r < 7; r++) {
        const int i = i0 + r;
        z[r] = (i < NSF) ? zr[i] : 0.0f;
    }
    float dd[6], pre[6];
    float tot = 0.f;   // scan input: EXCLUDES the final sample's dd (only used for its own
                       // alpha; including its ~1e10 magnitude destroys the prefix via rounding)
#pragma unroll
    for (int r = 0; r < 6; r++) {
        const int i = i0 + r;
        const float td = (i < NSF - 1) ? (z[r + 1] - z[r]) : 1e10f;
        dd[r] = g_sig_f[(size_t)b * NSF + i] * td * nrm;
        pre[r] = tot;
        if (i < NSF - 1) tot += dd[r];
    }
    const float excl = wscan_incl(tot) - tot;

    const float* rp = &g_rgb_f[((size_t)b * NSF + i0) * 3];
    float acc = 0.f, dep = 0.f, wz0 = 0.f, c0 = 0.f, c1 = 0.f, c2 = 0.f;
#pragma unroll
    for (int r = 0; r < 6; r++) {
        const float wi = (1.0f - __expf(-dd[r])) * __expf(-(excl + pre[r]));
        acc += wi;
        dep = fmaf(wi, z[r], dep);
        wz0 = fmaf(wi, g_z[i0 + r], wz0);     // samples_f[0] quirk: ray-0 z positions
        c0 = fmaf(wi, rp[3 * r + 0], c0);
        c1 = fmaf(wi, rp[3 * r + 1], c1);
        c2 = fmaf(wi, rp[3 * r + 2], c2);
    }
    acc = wred(acc); dep = wred(dep); wz0 = wred(wz0);
    c0 = wred(c0); c1 = wred(c1); c2 = wred(c2);
    if (lane == 0) {
        float* ob = out + (size_t)b * 16;
        ob[8]  = c0 + bkgd[0] * (1.0f - acc);
        ob[9]  = c1 + bkgd[1] * (1.0f - acc);
        ob[10] = c2 + bkgd[2] * (1.0f - acc);
        ob[11] = dep;
        ob[12] = acc;
        ob[13] = acc * org[0]  + wz0 * dirv[0];
        ob[14] = acc * org[1]  + wz0 * dirv[1];
        ob[15] = acc * org[2]  + wz0 * dirv[2];
    }
}

// ---------------- launch ----------------
extern "C" void kernel_launch(void* const* d_in, const int* in_sizes, int n_in,
                              void* d_out, int out_size)
{
    const float* org   = (const float*)d_in[0];
    const float* dirv  = (const float*)d_in[1];
    const float* nearp = (const float*)d_in[2];
    const float* farp  = (const float*)d_in[3];
    const float* bkgd  = (const float*)d_in[4];

    const float* w1c = (const float*)d_in[5];
    const float* b1c = (const float*)d_in[6];
    const float* w2c = (const float*)d_in[7];
    const float* b2c = (const float*)d_in[8];
    const float* wrc = (const float*)d_in[9];
    const float* brc = (const float*)d_in[10];
    const float* wdc = (const float*)d_in[11];
    const float* bdc = (const float*)d_in[12];

    const float* w1f = (const float*)d_in[13];
    const float* b1f = (const float*)d_in[14];
    const float* w2f = (const float*)d_in[15];
    const float* b2f = (const float*)d_in[16];
    const float* wrf = (const float*)d_in[17];
    const float* brf = (const float*)d_in[18];
    const float* wdf = (const float*)d_in[19];
    const float* bdf = (const float*)d_in[20];

    float* out = (float*)d_out;

    // coarse: 16384*64/16 = 65536 tiles; 4 warps * 8 tiles per block -> 2048 blocks
    mlp_mma_kernel<NCO, true, 8><<<2048, 128>>>(
        org, dirv, nearp, farp, w1c, b1c, w2c, b2c, wrc, brc, wdc, bdc);

    coarse_post_kernel<<<BATCH / 32, 32>>>(org, dirv, nearp, farp, bkgd, out);

    // fine: 16384*192/16 = 196608 tiles -> 6144 blocks
    mlp_mma_kernel<NSF, false, 8><<<6144, 128>>>(
        org, dirv, nearp, farp, w1f, b1f, w2f, b2f, wrf, brf, wdf, bdf);

    // warp-per-ray: 8 rays per 256-thread block -> 2048 blocks
    fine_render_kernel<<<BATCH / 8, 256>>>(org, dirv, bkgd, out);
}

// round 12
// speedup vs baseline: 4.1473x; 1.1184x over previous
#include <cuda_runtime.h>
#include <cuda_fp16.h>
#include <math.h>

#define BATCH 16384
#define NCO   64
#define NFI   128
#define NSF   192
#define HID   64

// ---------------- scratch (device globals; no allocation allowed) ----------------
__device__ float g_rgb_c[BATCH * NCO * 3];
__device__ float g_sig_c[BATCH * NCO];
__device__ float g_z    [BATCH * NSF];
__device__ float g_rgb_f[BATCH * NSF * 3];
__device__ float g_sig_f[BATCH * NSF];

__device__ __forceinline__ float sigmoidf_(float z) { return 1.0f / (1.0f + __expf(-z)); }

// split fp32 into fp16 hi + fp16 lo (hi+lo carries ~22 mantissa bits)
__device__ __forceinline__ void split_h(float v, unsigned short& hi, unsigned short& lo) {
    const __half h = __float2half_rn(v);
    hi = __half_as_ushort(h);
    lo = __half_as_ushort(__float2half_rn(v - __half2float(h)));
}
__device__ __forceinline__ unsigned pack2(unsigned short l, unsigned short h) {
    return (unsigned)l | ((unsigned)h << 16);
}

__device__ __forceinline__ void mma_f16(float& c0, float& c1, float& c2, float& c3,
    unsigned a0, unsigned a1, unsigned a2, unsigned a3, unsigned b0, unsigned b1) {
    asm("mma.sync.aligned.m16n8k16.row.col.f32.f16.f16.f32 "
        "{%0,%1,%2,%3},{%4,%5,%6,%7},{%8,%9},{%0,%1,%2,%3};"
        : "+f"(c0), "+f"(c1), "+f"(c2), "+f"(c3)
        : "r"(a0), "r"(a1), "r"(a2), "r"(a3), "r"(b0), "r"(b1));
}

// warp helpers
__device__ __forceinline__ float wred(float v) {
#pragma unroll
    for (int o = 16; o; o >>= 1) v += __shfl_xor_sync(0xffffffffu, v, o);
    return v;
}
__device__ __forceinline__ float wscan_incl(float v) {
    const int lane = threadIdx.x & 31;
    float x = v;
#pragma unroll
    for (int o = 1; o < 32; o <<= 1) {
        float n = __shfl_up_sync(0xffffffffu, x, o);
        if (lane >= o) x += n;
    }
    return x;
}

// ---------------- MLP via mma.sync f16 (3-term split), warp per 16-sample tile (R7) ----------------
template <int NS, bool COARSE, int TPW>
__global__ void __launch_bounds__(128) mlp_mma_kernel(
    const float* __restrict__ org,  const float* __restrict__ dirv,
    const float* __restrict__ nearp,const float* __restrict__ farp,
    const float* __restrict__ w1,   const float* __restrict__ b1,
    const float* __restrict__ w2,   const float* __restrict__ b2,
    const float* __restrict__ wr,   const float* __restrict__ br,
    const float* __restrict__ wd,   const float* __restrict__ bd)
{
    __shared__ __align__(16) uint4 sFragB[32 * 32];      // 16 KB
    __shared__ __align__(16) float sL1[HID * 4];
    __shared__ __align__(16) float sHD[HID * 4];
    __shared__ float sB2[HID];
    __shared__ float sBh[4];

    const int tid = threadIdx.x;
    for (int e = tid; e < 32 * 32; e += 128) {
        const int pair = e >> 5, lv = e & 31;
        const int nc = pair >> 2, kc = pair & 3;
        const int gv = lv >> 2, tv = lv & 3;
        const int n  = nc * 8 + gv;
        const int k0 = 16 * kc + 2 * tv;
        const int k2 = k0 + 8;
        unsigned short h00, l00, h01, l01, h20, l20, h21, l21;
        split_h(w2[(k0    ) * HID + n], h00, l00);
        split_h(w2[(k0 + 1) * HID + n], h01, l01);
        split_h(w2[(k2    ) * HID + n], h20, l20);
        split_h(w2[(k2 + 1) * HID + n], h21, l21);
        sFragB[e] = make_uint4(pack2(h00, h01), pack2(h20, h21),
                               pack2(l00, l01), pack2(l20, l21));
    }
    for (int i = tid; i < HID; i += 128) {
        sL1[4*i+0] = w1[i]; sL1[4*i+1] = w1[64+i]; sL1[4*i+2] = w1[128+i]; sL1[4*i+3] = b1[i];
        sHD[4*i+0] = wr[3*i]; sHD[4*i+1] = wr[3*i+1]; sHD[4*i+2] = wr[3*i+2]; sHD[4*i+3] = wd[i];
        sB2[i] = b2[i];
    }
    if (tid == 0) { sBh[0] = br[0]; sBh[1] = br[1]; sBh[2] = br[2]; sBh[3] = bd[0]; }
    __syncthreads();

    const int lane = tid & 31;
    const int gid  = lane >> 2;
    const int tig  = lane & 3;
    const int warpGlobal = blockIdx.x * 4 + (tid >> 5);

#pragma unroll 1
    for (int it = 0; it < TPW; ++it) {
        const int tileIdx = warpGlobal * TPW + it;
        const int s0 = tileIdx * 16;
        const int b  = s0 / NS;

        const float ox = org[3*b], oy = org[3*b+1], oz = org[3*b+2];
        const float dx = dirv[3*b], dy = dirv[3*b+1], dz = dirv[3*b+2];
        float t0, t1;
        if (COARSE) {
            const float nb = nearp[b], fb = farp[b];
            const int i0 = (s0 % NS) + gid, i1 = i0 + 8;
            float q0 = (i0 == 63) ? 1.0f : (float)i0 * (1.0f / 63.0f);
            float q1 = (i1 == 63) ? 1.0f : (float)i1 * (1.0f / 63.0f);
            t0 = nb * (1.0f - q0) + fb * q0;
            t1 = nb * (1.0f - q1) + fb * q1;
        } else {
            t0 = g_z[s0 + gid];
            t1 = g_z[s0 + gid + 8];
        }
        const float x00 = fmaf(t0, dx, ox), x01 = fmaf(t0, dy, oy), x02 = fmaf(t0, dz, oz);
        const float x10 = fmaf(t1, dx, ox), x11 = fmaf(t1, dy, oy), x12 = fmaf(t1, dz, oz);

        unsigned Ah[4][4], Al[4][4];
#pragma unroll
        for (int kc = 0; kc < 4; kc++) {
            unsigned short hg[4], lg[4], hG[4], lG[4];
#pragma unroll
            for (int q = 0; q < 4; q++) {
                const int c = 16 * kc + ((q >> 1) << 3) + 2 * tig + (q & 1);
                const float4 L = *(const float4*)&sL1[4 * c];
                const float hA = fmaxf(fmaf(x02, L.z, fmaf(x01, L.y, fmaf(x00, L.x, L.w))), 0.0f);
                const float hB = fmaxf(fmaf(x12, L.z, fmaf(x11, L.y, fmaf(x10, L.x, L.w))), 0.0f);
                split_h(hA, hg[q], lg[q]);
                split_h(hB, hG[q], lG[q]);
            }
            Ah[kc][0] = pack2(hg[0], hg[1]); Ah[kc][1] = pack2(hG[0], hG[1]);
            Ah[kc][2] = pack2(hg[2], hg[3]); Ah[kc][3] = pack2(hG[2], hG[3]);
            Al[kc][0] = pack2(lg[0], lg[1]); Al[kc][1] = pack2(lG[0], lG[1]);
            Al[kc][2] = pack2(lg[2], lg[3]); Al[kc][3] = pack2(lG[2], lG[3]);
        }

        float hp0[4] = {0.f, 0.f, 0.f, 0.f};
        float hp1[4] = {0.f, 0.f, 0.f, 0.f};
#pragma unroll 1
        for (int nc = 0; nc < 8; nc++) {
            const int j0 = nc * 8 + 2 * tig;
            float c0 = sB2[j0], c1 = sB2[j0 + 1];
            float c2 = c0, c3 = c1;
            const uint4* frag = &sFragB[(nc * 4) * 32 + lane];
#pragma unroll
            for (int kc = 0; kc < 4; kc++) {
                const uint4 f = frag[kc * 32];
                mma_f16(c0, c1, c2, c3,
                        Ah[kc][0], Ah[kc][1], Ah[kc][2], Ah[kc][3], f.x, f.y);
                mma_f16(c0, c1, c2, c3,
                        Al[kc][0], Al[kc][1], Al[kc][2], Al[kc][3], f.x, f.y);
                mma_f16(c0, c1, c2, c3,
                        Ah[kc][0], Ah[kc][1], Ah[kc][2], Ah[kc][3], f.z, f.w);
            }
            const float4 H0 = *(const float4*)&sHD[4 * j0];
            const float4 H1 = *(const float4*)&sHD[4 * (j0 + 1)];
            const float v00 = fmaxf(c0, 0.f), v01 = fmaxf(c1, 0.f);
            const float v10 = fmaxf(c2, 0.f), v11 = fmaxf(c3, 0.f);
            hp0[0] = fmaf(v00, H0.x, fmaf(v01, H1.x, hp0[0]));
            hp0[1] = fmaf(v00, H0.y, fmaf(v01, H1.y, hp0[1]));
            hp0[2] = fmaf(v00, H0.z, fmaf(v01, H1.z, hp0[2]));
            hp0[3] = fmaf(v00, H0.w, fmaf(v01, H1.w, hp0[3]));
            hp1[0] = fmaf(v10, H0.x, fmaf(v11, H1.x, hp1[0]));
            hp1[1] = fmaf(v10, H0.y, fmaf(v11, H1.y, hp1[1]));
            hp1[2] = fmaf(v10, H0.z, fmaf(v11, H1.z, hp1[2]));
            hp1[3] = fmaf(v10, H0.w, fmaf(v11, H1.w, hp1[3]));
        }

#pragma unroll
        for (int c = 0; c < 4; c++) {
            hp0[c] += __shfl_xor_sync(0xffffffffu, hp0[c], 1);
            hp0[c] += __shfl_xor_sync(0xffffffffu, hp0[c], 2);
            hp1[c] += __shfl_xor_sync(0xffffffffu, hp1[c], 1);
            hp1[c] += __shfl_xor_sync(0xffffffffu, hp1[c], 2);
        }
        if (tig == 0) {
            float* rgb = COARSE ? g_rgb_c : g_rgb_f;
            float* sg  = COARSE ? g_sig_c : g_sig_f;
            const int sA = s0 + gid, sB = s0 + gid + 8;
            rgb[3*sA+0] = sigmoidf_(hp0[0] + sBh[0]);
            rgb[3*sA+1] = sigmoidf_(hp0[1] + sBh[1]);
            rgb[3*sA+2] = sigmoidf_(hp0[2] + sBh[2]);
            sg[sA] = fmaxf(hp0[3] + sBh[3], 0.f);
            rgb[3*sB+0] = sigmoidf_(hp1[0] + sBh[0]);
            rgb[3*sB+1] = sigmoidf_(hp1[1] + sBh[1]);
            rgb[3*sB+2] = sigmoidf_(hp1[2] + sBh[2]);
            sg[sB] = fmaxf(hp1[3] + sBh[3], 0.f);
        }
    }
}

// ---------------- coarse: warp-per-ray render + CDF + inverse sampling + merge ----------------
// (scan input EXCLUDES the i=63 sample's dd — its 1e10 magnitude would destroy the
//  transmittance prefix via fp rounding; it only ever feeds its own alpha)
__global__ void __launch_bounds__(256) coarse_post_kernel(
    const float* __restrict__ org, const float* __restrict__ dirv,
    const float* __restrict__ nearp, const float* __restrict__ farp,
    const float* __restrict__ bkgd, float* __restrict__ out)
{
    __shared__ float scdf[8][64];
    __shared__ float szb[8][128];

    const int warp = threadIdx.x >> 5;
    const int lane = threadIdx.x & 31;
    const int b = blockIdx.x * 8 + warp;

    const float nb = nearp[b], fb = farp[b];
    const float n0 = nearp[0], f0 = farp[0];
    const float dxx = dirv[3 * b], dyy = dirv[3 * b + 1], dzz = dirv[3 * b + 2];
    const float nrm = sqrtf(dxx * dxx + dyy * dyy + dzz * dzz);

    auto TV = [&](int i) -> float {
        float tq = (i == 63) ? 1.0f : (float)i * (1.0f / 63.0f);
        return nb * (1.0f - tq) + fb * tq;
    };
    auto TV0 = [&](int i) -> float {
        float tq = (i == 63) ? 1.0f : (float)i * (1.0f / 63.0f);
        return n0 * (1.0f - tq) + f0 * tq;
    };

    // ---- phase 1: render (lane covers samples 2l, 2l+1) ----
    const int i0 = 2 * lane, i1 = i0 + 1;
    const float tA = TV(i0), tB = TV(i1);
    const float tC = (i1 < 63) ? TV(i1 + 1) : tB;
    const float td0 = tB - tA;
    const float td1 = (i1 < 63) ? (tC - tB) : 1e10f;
    const float dd0 = g_sig_c[b * 64 + i0] * td0 * nrm;
    const float dd1 = g_sig_c[b * 64 + i1] * td1 * nrm;
    const float tot = dd0 + ((i1 < 63) ? dd1 : 0.0f);   // exclude i=63 dd from scan
    const float excl = wscan_incl(tot) - tot;
    const float w0 = (1.0f - __expf(-dd0)) * __expf(-excl);
    const float w1 = (1.0f - __expf(-dd1)) * __expf(-(excl + dd0));

    const float* rp = &g_rgb_c[(size_t)(b * 64 + i0) * 3];
    float acc = w0 + w1;
    float dep = w0 * tA + w1 * tB;
    float wt0 = w0 * TV0(i0) + w1 * TV0(i1);
    float c0 = w0 * rp[0] + w1 * rp[3];
    float c1 = w0 * rp[1] + w1 * rp[4];
    float c2 = w0 * rp[2] + w1 * rp[5];
    acc = wred(acc); dep = wred(dep); wt0 = wred(wt0);
    c0 = wred(c0); c1 = wred(c1); c2 = wred(c2);
    if (lane == 0) {
        float* ob = out + (size_t)b * 16;
        ob[0] = c0 + bkgd[0] * (1.0f - acc);
        ob[1] = c1 + bkgd[1] * (1.0f - acc);
        ob[2] = c2 + bkgd[2] * (1.0f - acc);
        ob[3] = dep;
        ob[4] = acc;
        ob[5] = acc * org[0]  + wt0 * dirv[0];
        ob[6] = acc * org[1]  + wt0 * dirv[1];
        ob[7] = acc * org[2]  + wt0 * dirv[2];
    }

    // ---- phase 2: cdf over w[1..62] ----
    const float wsl = ((i0 >= 1) ? w0 : 0.f) + ((i1 <= 62) ? w1 : 0.f);
    const float ws = wred(wsl);
    const float pad = fmaxf(1e-5f - ws, 0.0f);
    const float add = pad * (1.0f / 62.0f);
    const float inv = 1.0f / (ws + pad);
    const float pv0 = (i0 >= 1 && i0 <= 61) ? (w0 + add) * inv : 0.f;
    const float pv1 = (i1 >= 1 && i1 <= 61) ? (w1 + add) * inv : 0.f;
    const float t2 = pv0 + pv1;
    const float e2 = wscan_incl(t2) - t2;
    if (i0 >= 1 && i0 <= 61) scdf[warp][i0] = fminf(e2 + pv0, 1.0f);
    if (i1 <= 61)            scdf[warp][i1] = fminf(e2 + pv0 + pv1, 1.0f);
    if (lane == 0)  scdf[warp][0]  = 0.0f;
    if (lane == 31) scdf[warp][62] = 1.0f;
    __syncwarp();

    // ---- phase 3: inverse-CDF samples (4 per lane) + merged placement by rank ----
    auto BIN = [&](int k) -> float { return 0.5f * (TV(k) + TV(k + 1)); };
    const float ueps = 1.1920929e-07f;
    const float du = (1.0f - ueps) * (1.0f / 127.0f);
    const size_t base = (size_t)b * NSF;
    float zq[4];
#pragma unroll
    for (int q = 0; q < 4; q++) {
        const int s = 4 * lane + q;
        const float u = (s == 127) ? (1.0f - ueps) : (float)s * du;
        int idx = 0;
#pragma unroll
        for (int st = 32; st >= 1; st >>= 1) {
            const int nx = idx + st;
            if (nx <= 61 && scdf[warp][nx] <= u) idx = nx;
        }
        const float gg0 = scdf[warp][idx], gg1 = scdf[warp][idx + 1];
        float tt = (u - gg0) / (gg1 - gg0);
        if (!(tt == tt)) tt = 0.0f;
        tt = fminf(fmaxf(tt, 0.0f), 1.0f);
        const float bb0 = BIN(idx);
        zq[q] = fmaf(tt, BIN(idx + 1) - bb0, bb0);
        szb[warp][s] = zq[q];
    }
    __syncwarp();
#pragma unroll
    for (int q = 0; q < 4; q++) {
        const int s = 4 * lane + q;
        const float z = zq[q];
        int c = 0;                       // #{i in [0,64): TV(i) <= z}
#pragma unroll
        for (int st = 64; st >= 1; st >>= 1) {
            const int nx = c + st;
            if (nx <= 64 && TV(nx - 1) <= z) c = nx;
        }
        g_z[base + s + c] = z;
    }
#pragma unroll
    for (int q = 0; q < 2; q++) {
        const int ti = 2 * lane + q;
        const float tv = TV(ti);
        int c = 0;                       // #{s: zb[s] < tv}  (strict: ties put t first)
#pragma unroll
        for (int st = 128; st >= 1; st >>= 1) {
            const int nx = c + st;
            if (nx <= 128 && szb[warp][nx - 1] < tv) c = nx;
        }
        g_z[base + ti + c] = tv;
    }
}

// ---------------- fine render: warp-per-ray (validated) ----------------
__global__ void __launch_bounds__(256) fine_render_kernel(
    const float* __restrict__ org, const float* __restrict__ dirv,
    const float* __restrict__ bkgd, float* __restrict__ out)
{
    const int warp = threadIdx.x >> 5;
    const int lane = threadIdx.x & 31;
    const int b = blockIdx.x * 8 + warp;

    const float dxx = dirv[3*b+0], dyy = dirv[3*b+1], dzz = dirv[3*b+2];
    const float nrm = sqrtf(dxx*dxx + dyy*dyy + dzz*dzz);

    const float* zr = g_z + (size_t)b * NSF;
    const int i0 = 6 * lane;

    float z[7];
#pragma unroll
    for (int r = 0; r < 7; r++) {
        const int i = i0 + r;
        z[r] = (i < NSF) ? zr[i] : 0.0f;
    }
    float dd[6], pre[6];
    float tot = 0.f;
#pragma unroll
    for (int r = 0; r < 6; r++) {
        const int i = i0 + r;
        const float td = (i < NSF - 1) ? (z[r + 1] - z[r]) : 1e10f;
        dd[r] = g_sig_f[(size_t)b * NSF + i] * td * nrm;
        pre[r] = tot;
        if (i < NSF - 1) tot += dd[r];
    }
    const float excl = wscan_incl(tot) - tot;

    const float* rp = &g_rgb_f[((size_t)b * NSF + i0) * 3];
    float acc = 0.f, dep = 0.f, wz0 = 0.f, c0 = 0.f, c1 = 0.f, c2 = 0.f;
#pragma unroll
    for (int r = 0; r < 6; r++) {
        const float wi = (1.0f - __expf(-dd[r])) * __expf(-(excl + pre[r]));
        acc += wi;
        dep = fmaf(wi, z[r], dep);
        wz0 = fmaf(wi, g_z[i0 + r], wz0);     // samples_f[0] quirk: ray-0 z positions
        c0 = fmaf(wi, rp[3 * r + 0], c0);
        c1 = fmaf(wi, rp[3 * r + 1], c1);
        c2 = fmaf(wi, rp[3 * r + 2], c2);
    }
    acc = wred(acc); dep = wred(dep); wz0 = wred(wz0);
    c0 = wred(c0); c1 = wred(c1); c2 = wred(c2);
    if (lane == 0) {
        float* ob = out + (size_t)b * 16;
        ob[8]  = c0 + bkgd[0] * (1.0f - acc);
        ob[9]  = c1 + bkgd[1] * (1.0f - acc);
        ob[10] = c2 + bkgd[2] * (1.0f - acc);
        ob[11] = dep;
        ob[12] = acc;
        ob[13] = acc * org[0]  + wz0 * dirv[0];
        ob[14] = acc * org[1]  + wz0 * dirv[1];
        ob[15] = acc * org[2]  + wz0 * dirv[2];
    }
}

// ---------------- launch ----------------
extern "C" void kernel_launch(void* const* d_in, const int* in_sizes, int n_in,
                              void* d_out, int out_size)
{
    const float* org   = (const float*)d_in[0];
    const float* dirv  = (const float*)d_in[1];
    const float* nearp = (const float*)d_in[2];
    const float* farp  = (const float*)d_in[3];
    const float* bkgd  = (const float*)d_in[4];

    const float* w1c = (const float*)d_in[5];
    const float* b1c = (const float*)d_in[6];
    const float* w2c = (const float*)d_in[7];
    const float* b2c = (const float*)d_in[8];
    const float* wrc = (const float*)d_in[9];
    const float* brc = (const float*)d_in[10];
    const float* wdc = (const float*)d_in[11];
    const float* bdc = (const float*)d_in[12];

    const float* w1f = (const float*)d_in[13];
    const float* b1f = (const float*)d_in[14];
    const float* w2f = (const float*)d_in[15];
    const float* b2f = (const float*)d_in[16];
    const float* wrf = (const float*)d_in[17];
    const float* brf = (const float*)d_in[18];
    const float* wdf = (const float*)d_in[19];
    const float* bdf = (const float*)d_in[20];

    float* out = (float*)d_out;

    // coarse: 16384*64/16 = 65536 tiles; 4 warps * 8 tiles per block -> 2048 blocks
    mlp_mma_kernel<NCO, true, 8><<<2048, 128>>>(
        org, dirv, nearp, farp, w1c, b1c, w2c, b2c, wrc, brc, wdc, bdc);

    // warp-per-ray: 8 rays per 256-thread block -> 2048 blocks
    coarse_post_kernel<<<BATCH / 8, 256>>>(org, dirv, nearp, farp, bkgd, out);

    // fine: 16384*192/16 = 196608 tiles -> 6144 blocks
    mlp_mma_kernel<NSF, false, 8><<<6144, 128>>>(
        org, dirv, nearp, farp, w1f, b1f, w2f, b2f, wrf, brf, wdf, bdf);

    fine_render_kernel<<<BATCH / 8, 256>>>(org, dirv, bkgd, out);
}